// round 8
// baseline (speedup 1.0000x reference)
#include <cuda_runtime.h>
#include <cuda_fp16.h>
#include <math.h>

typedef unsigned long long u64;

#define NIMG 16
#define NO   192
#define Hh   160
#define Wd   160
#define HW   25600
#define PAD  36

#define KHKW3 2916
#define P3    9
#define A3    26244
#define U3IMG 1679616
#define KHKW5 1024
#define P5    25
#define A5    25600
#define U5IMG 1638400
#define NPI   560

// ---------------- scratch ----------------
__device__ __align__(16) __half g_ex[(size_t)NIMG*NO*HW];
__device__ __align__(16) __half g_u3[(size_t)NIMG*U3IMG];
__device__ __align__(16) __half g_u5[(size_t)NIMG*U5IMG];
__device__ __align__(16) float g_sf3[NIMG*P3*KHKW3];
__device__ __align__(16) float g_sf5[NIMG*P5*KHKW5];
__device__ float g_Z[NPI], g_S[NPI*64], g_Pm[NPI*64];
__device__ float g_gt[NPI*64], g_veff[NPI*64], g_beff[NPI];
__device__ __align__(16) float g_Wall[256*64];   // rows 0..191: fus@res [k][o]; 192..255: fus^T [c][o]
__device__ float g_vb[64];
__device__ __align__(16) float4 g_expWt4[64*64]; // [c][ob] -> (w_a0, w_a1, w_a2, 0)

// ---------------- helpers ----------------
__device__ __forceinline__ u64 pk2(float lo, float hi){
    u64 r; asm("mov.b64 %0,{%1,%2};":"=l"(r):"f"(lo),"f"(hi)); return r;
}
__device__ __forceinline__ void fma2(u64 &d, u64 a, u64 b){
    asm("fma.rn.f32x2 %0,%1,%2,%3;":"=l"(d):"l"(a),"l"(b),"l"(d));
}
__device__ __forceinline__ float2 up2(u64 v){
    float2 f; asm("mov.b64 {%0,%1},%2;":"=f"(f.x),"=f"(f.y):"l"(v)); return f;
}
__device__ __forceinline__ float sigf(float x){ return 1.f/(1.f+expf(-x)); }
__device__ __forceinline__ int cover3(int h, int* r){
    int n=0;
    #pragma unroll
    for(int i=0;i<3;i++){ int lo=53*i; if(h>=lo && h<=lo+53) r[n++]=i; }
    return n;
}

// ================ K0a: zero accumulators ================
__global__ void k_zero(){
    int i = blockIdx.x*256 + threadIdx.x;
    if(i < NPI) g_Z[i]=0.f;
    if(i < NPI*64){ g_S[i]=0.f; g_Pm[i]=0.f; }
}

// ================ K0b: weight prep ================
__global__ void k_wprep(const float* __restrict__ exp_w, const float* __restrict__ res_w,
                        const float* __restrict__ res_b, const float* __restrict__ fus_w,
                        const float* __restrict__ fus_b){
    int t = threadIdx.x;
    for(int i=t;i<64*64;i+=256){
        int c=i>>6, ob=i&63;
        g_expWt4[i] = make_float4(exp_w[ob*64+c], exp_w[(ob+64)*64+c], exp_w[(ob+128)*64+c], 0.f);
    }
    for(int i=t;i<NO*64;i+=256){
        int k=i/64, o=i%64; float s=0.f;
        for(int c=0;c<64;c++) s += fus_w[o*64+c]*res_w[c*NO+k];
        g_Wall[i]=s;
    }
    for(int i=t;i<64*64;i+=256){ int c=i/64, o=i%64; g_Wall[(192+c)*64+o]=fus_w[o*64+c]; }
    for(int o=t;o<64;o+=256){
        float s=fus_b[o];
        for(int c=0;c<64;c++) s += fus_w[o*64+c]*res_b[c];
        g_vb[o]=s;
    }
}

// ================ K1: ex = Wexp @ x + fused win1 stats ================
__global__ void __launch_bounds__(256) k1(const float* __restrict__ x,
                                          const float* __restrict__ exp_b,
                                          const float* __restrict__ wq,
                                          const float* __restrict__ wqb){
    __shared__ __align__(16) float xs[64*PAD];
    __shared__ float exs0[64*33];
    __shared__ float es[32];
    int t = threadIdx.x;
    int wt = blockIdx.x, h = blockIdx.y, n = blockIdx.z;
    int w0 = wt*32;

    const float* xp = x + (size_t)n*64*HW + (size_t)h*Wd + w0;
    for(int i=t;i<512;i+=256){
        int c=i>>3, grp=(i&7)*4;
        *(float4*)&xs[c*PAD+grp] = *(const float4*)&xp[(size_t)c*HW+grp];
    }
    __syncthreads();

    int ob = t&63, pg = t>>6, pb = pg*8;
    u64 acc[3][4];
    #pragma unroll
    for(int a=0;a<3;a++)
        #pragma unroll
        for(int j=0;j<4;j++) acc[a][j]=0ull;
    for(int c=0;c<64;c++){
        u64 xv[4];
        #pragma unroll
        for(int j=0;j<4;j++) xv[j]=*(const u64*)&xs[c*PAD+pb+j*2];
        float4 wv = __ldg(&g_expWt4[(c<<6) + ob]);
        u64 wp0 = pk2(wv.x,wv.x), wp1 = pk2(wv.y,wv.y), wp2 = pk2(wv.z,wv.z);
        #pragma unroll
        for(int j=0;j<4;j++) fma2(acc[0][j], wp0, xv[j]);
        #pragma unroll
        for(int j=0;j<4;j++) fma2(acc[1][j], wp1, xv[j]);
        #pragma unroll
        for(int j=0;j<4;j++) fma2(acc[2][j], wp2, xv[j]);
    }
    __half* exg = g_ex + (size_t)n*NO*HW + (size_t)h*Wd + w0;
    #pragma unroll
    for(int a=0;a<3;a++){
        float b = exp_b[ob+a*64];
        float2 v0=up2(acc[a][0]), v1=up2(acc[a][1]), v2=up2(acc[a][2]), v3=up2(acc[a][3]);
        if(a==0){
            float* d = &exs0[ob*33 + pb];
            d[0]=v0.x+b; d[1]=v0.y+b; d[2]=v1.x+b; d[3]=v1.y+b;
            d[4]=v2.x+b; d[5]=v2.y+b; d[6]=v3.x+b; d[7]=v3.y+b;
        }
        __half2 h0=__floats2half2_rn(v0.x+b, v0.y+b);
        __half2 h1=__floats2half2_rn(v1.x+b, v1.y+b);
        __half2 h2=__floats2half2_rn(v2.x+b, v2.y+b);
        __half2 h3=__floats2half2_rn(v3.x+b, v3.y+b);
        uint4 pk;
        pk.x=*(unsigned*)&h0; pk.y=*(unsigned*)&h1;
        pk.z=*(unsigned*)&h2; pk.w=*(unsigned*)&h3;
        *(uint4*)&exg[(size_t)(ob+a*64)*HW + pb] = pk;
    }
    __syncthreads();

    if(t<32){
        float qd = wqb[0];
        #pragma unroll
        for(int c=0;c<64;c++) qd += wq[c]*exs0[c*33+t];
        float e = expf(qd);
        es[t]=e;
        float z=e;
        for(int off=16;off;off>>=1) z += __shfl_xor_sync(0xffffffffu,z,off);
        if(t==0) atomicAdd(&g_Z[n], z);
    }
    __syncthreads();
    if(t<64){
        float Ps=0.f, Ss=0.f;
        #pragma unroll
        for(int px=0;px<32;px++){ float v=exs0[t*33+px]; Ps+=v; Ss+=v*es[px]; }
        atomicAdd(&g_S[n*64+t], Ss);
        atomicAdd(&g_Pm[n*64+t], Ps);
    }
}

// ================ K2: repack into unfold order (warp-per-ci, fp16) ================
__global__ void __launch_bounds__(256) k2_5(){
    __shared__ __align__(16) __half rb[8][800];
    int y = blockIdx.x, n = blockIdx.y;
    int wp = threadIdx.x >> 5, lane = threadIdx.x & 31;
    for(int cit=0; cit<8; cit++){
        int ci = cit*8 + wp;
        const __half* src = g_ex + (size_t)n*NO*HW + (size_t)(128+ci)*HW;
        #pragma unroll
        for(int ph=0; ph<5; ph++){
            const __half2* row2 = (const __half2*)(src + (size_t)(ph*32+y)*Wd);
            #pragma unroll
            for(int it=0; it<3; it++){
                int idx = lane + it*32;
                if(idx<80){
                    __half2 v = row2[idx];
                    int w = idx*2, pw = w>>5, xx = w&31;
                    rb[wp][xx*25 + ph*5 + pw]     = __low2half(v);
                    rb[wp][(xx+1)*25 + ph*5 + pw] = __high2half(v);
                }
            }
        }
        __syncwarp();
        uint4* dst = (uint4*)(g_u5 + (size_t)n*U5IMG + (size_t)(ci*1024 + y*32)*25);
        const uint4* s = (const uint4*)rb[wp];
        #pragma unroll
        for(int it=0; it<4; it++){
            int k = lane + it*32;
            if(k < 100) dst[k] = s[k];
        }
        __syncwarp();
    }
}
__global__ void __launch_bounds__(256) k2_3(){
    __shared__ __align__(16) __half rb[8][488];
    int yy = blockIdx.x, n = blockIdx.y;
    int wp = threadIdx.x >> 5, lane = threadIdx.x & 31;
    for(int cit=0; cit<8; cit++){
        int ci = cit*8 + wp;
        const __half* src = g_ex + (size_t)n*NO*HW + (size_t)(64+ci)*HW;
        #pragma unroll
        for(int ph=0; ph<3; ph++){
            const __half2* row2 = (const __half2*)(src + (size_t)(53*ph+yy)*Wd);
            #pragma unroll
            for(int it=0; it<3; it++){
                int idx = lane + it*32;
                if(idx<80){
                    __half2 v = row2[idx];
                    int w0_ = idx*2;
                    __half hv[2] = {__low2half(v), __high2half(v)};
                    #pragma unroll
                    for(int hh=0; hh<2; hh++){
                        int w = w0_ + hh;
                        #pragma unroll
                        for(int pw=0; pw<3; pw++){
                            int xx = w - 53*pw;
                            if(xx>=0 && xx<54) rb[wp][xx*9 + ph*3 + pw] = hv[hh];
                        }
                    }
                }
            }
        }
        __syncwarp();
        unsigned* dst = (unsigned*)(g_u3 + (size_t)n*U3IMG + (size_t)ci*A3 + (size_t)yy*486);
        const unsigned* s = (const unsigned*)rb[wp];
        #pragma unroll
        for(int it=0; it<8; it++){
            int k = lane + it*32;
            if(k < 243) dst[k] = s[k];
        }
        __syncwarp();
    }
}

// ================ K3: stats (fp16 smem, q-tile 128) ================
__global__ void __launch_bounds__(256) k_stats(const __half* __restrict__ ub, int khkw,
                                               size_t imgstride, int piBase,
                                               const float* __restrict__ wq,
                                               const float* __restrict__ wqb){
    __shared__ __half Vs[64*130];
    __shared__ float part[4*128];
    __shared__ float es[128];
    int q0 = blockIdx.x*128, bp = blockIdx.y, n = blockIdx.z;
    int t = threadIdx.x;
    const __half* base = ub + (size_t)n*imgstride + (size_t)bp*64*khkw + q0;
    int qlim = khkw - q0; if(qlim>128) qlim=128;

    for(int i=t;i<4096;i+=256){
        int c=i>>6, j2=i&63;
        unsigned v = 0;
        if(j2*2 < qlim) v = *(const unsigned*)&base[(size_t)c*khkw + j2*2];
        *(unsigned*)&Vs[c*130 + j2*2] = v;
    }
    __syncthreads();
    {
        int j2=t&63, cg=t>>6;
        float sx=0.f, sy=0.f;
        #pragma unroll 8
        for(int cc=cg*16; cc<cg*16+16; cc++){
            float2 f = __half22float2(*(const __half2*)&Vs[cc*130 + j2*2]);
            float w = wq[cc];
            sx += w*f.x; sy += w*f.y;
        }
        part[cg*128 + j2*2]   = sx;
        part[cg*128 + j2*2+1] = sy;
    }
    __syncthreads();
    int pi = piBase + n*gridDim.y + bp;
    if(t<128){
        float qd = part[t]+part[128+t]+part[256+t]+part[384+t] + wqb[0];
        float e = (t<qlim) ? expf(qd) : 0.f;
        es[t]=e;
        float z=e;
        for(int off=16;off;off>>=1) z += __shfl_xor_sync(0xffffffffu,z,off);
        if((t&31)==0) atomicAdd(&g_Z[pi], z);
    }
    __syncthreads();
    {
        int c=t&63, jg=t>>6;
        float ss=0.f, pm=0.f;
        #pragma unroll 8
        for(int j2=jg*16; j2<jg*16+16; j2++){
            float2 f = __half22float2(*(const __half2*)&Vs[c*130 + j2*2]);
            ss += f.x*es[2*j2] + f.y*es[2*j2+1];
            pm += f.x + f.y;
        }
        atomicAdd(&g_S[pi*64+c], ss);
        atomicAdd(&g_Pm[pi*64+c], pm);
    }
}

// ================ K4: per-pseudo-image finalize ================
__global__ void __launch_bounds__(64) k4(const float* __restrict__ chwv_w, const float* __restrict__ chwv_b,
                                         const float* __restrict__ chwz_w, const float* __restrict__ chwz_b,
                                         const float* __restrict__ ln_g,  const float* __restrict__ ln_b,
                                         const float* __restrict__ spwq_w,const float* __restrict__ spwq_b,
                                         const float* __restrict__ spwv_w,const float* __restrict__ spwv_b){
    int p = blockIdx.x, t = threadIdx.x;
    float hw = (p<16) ? 25600.f : ((p<160) ? 2916.f : 1024.f);
    __shared__ float xbar[64], pmean[64], wz[32], red[64], swq[32];

    float Zinv = 1.f/g_Z[p];
    xbar[t]  = g_S[p*64+t]*Zinv;
    pmean[t] = g_Pm[p*64+t]/hw;
    __syncthreads();

    if(t<32){
        float s = chwv_b[t];
        for(int c=0;c<64;c++) s += chwv_w[t*64+c]*xbar[c];
        wz[t]=s;
    }
    __syncthreads();

    float z = chwz_b[t];
    for(int j=0;j<32;j++) z += chwz_w[t*32+j]*wz[j];

    red[t]=z; __syncthreads();
    for(int s=32;s>0;s>>=1){ if(t<s) red[t]+=red[t+s]; __syncthreads(); }
    float mu = red[0]*(1.f/64.f); __syncthreads();
    float d = z-mu;
    red[t]=d*d; __syncthreads();
    for(int s=32;s>0;s>>=1){ if(t<s) red[t]+=red[t+s]; __syncthreads(); }
    float var = red[0]*(1.f/64.f);

    float zn = d*rsqrtf(var+1e-5f)*ln_g[t] + ln_b[t];
    g_gt[p*64+t] = sigf(zn);
    __syncthreads();

    if(t<32){
        float s = spwq_b[t];
        for(int c=0;c<64;c++) s += spwq_w[t*64+c]*pmean[c];
        float m=s;
        for(int off=16;off;off>>=1) m=fmaxf(m,__shfl_xor_sync(0xffffffffu,m,off));
        float e=expf(s-m), sum=e;
        for(int off=16;off;off>>=1) sum+=__shfl_xor_sync(0xffffffffu,sum,off);
        swq[t]=e/sum;
    }
    __syncthreads();

    float v=0.f;
    for(int j=0;j<32;j++) v += swq[j]*spwv_w[j*64+t];
    g_veff[p*64+t]=v;
    if(t==0){
        float b=0.f;
        for(int j=0;j<32;j++) b += swq[j]*spwv_b[j];
        g_beff[p]=b;
    }
}

// ================ K5: s-field (fp16 smem, q-tile 128) ================
__global__ void __launch_bounds__(256) k_sfield(const __half* __restrict__ ub, int khkw,
                                                size_t imgstride, int piBase,
                                                float* __restrict__ sf){
    __shared__ __half Vs[64*130];
    __shared__ float part[4*128];
    __shared__ float ve[64];
    int q0 = blockIdx.x*128, bp = blockIdx.y, n = blockIdx.z;
    int t = threadIdx.x;
    int pi = piBase + n*gridDim.y + bp;
    const __half* base = ub + (size_t)n*imgstride + (size_t)bp*64*khkw + q0;
    int qlim = khkw - q0; if(qlim>128) qlim=128;

    if(t<64) ve[t]=g_veff[pi*64+t];
    for(int i=t;i<4096;i+=256){
        int c=i>>6, j2=i&63;
        unsigned v = 0;
        if(j2*2 < qlim) v = *(const unsigned*)&base[(size_t)c*khkw + j2*2];
        *(unsigned*)&Vs[c*130 + j2*2] = v;
    }
    __syncthreads();
    {
        int j2=t&63, cg=t>>6;
        float sx=0.f, sy=0.f;
        #pragma unroll 8
        for(int cc=cg*16; cc<cg*16+16; cc++){
            float2 f = __half22float2(*(const __half2*)&Vs[cc*130 + j2*2]);
            float w = ve[cc];
            sx += w*f.x; sy += w*f.y;
        }
        part[cg*128 + j2*2]   = sx;
        part[cg*128 + j2*2+1] = sy;
    }
    __syncthreads();
    if(t<128 && t<qlim){
        float sd = part[t]+part[128+t]+part[256+t]+part[384+t] + g_beff[pi];
        sf[(size_t)n*(gridDim.y*khkw) + (size_t)bp*khkw + q0 + t] = sigf(sd);
    }
}

// ================ K6: staged-sf multiplier + GEMM (4ob x 2px) ================
__global__ void __launch_bounds__(256) k6(const float* __restrict__ x, float* __restrict__ out){
    __shared__ __align__(16) float vs[256*PAD];   // rows 0..191 ex', rows 192..255 x
    __shared__ float sm3[4*32*9];                 // [s][pix][bp0..8]
    __shared__ float sm5[32*25];                  // [pix][bp0..24]
    __shared__ float s1s[32], icntS[32];
    __shared__ int q5s[32], cp05s[32];
    __shared__ int q3s[4][32], cp03s[4][32];
    __shared__ int nsegS[32];

    int t = threadIdx.x;
    int wt = blockIdx.x, h = blockIdx.y, n = blockIdx.z;
    int w0 = wt*32;

    const __half* exg = g_ex + (size_t)n*NO*HW + (size_t)h*Wd + w0;
    for(int i=t;i<768;i+=256){
        int k=i>>2, q=(i&3)*8;
        uint4 raw = *(const uint4*)&exg[(size_t)k*HW + q];
        __half2* hp = (__half2*)&raw;
        float2 f0=__half22float2(hp[0]), f1=__half22float2(hp[1]);
        float2 f2=__half22float2(hp[2]), f3=__half22float2(hp[3]);
        float* d = &vs[k*PAD+q];
        d[0]=f0.x; d[1]=f0.y; d[2]=f1.x; d[3]=f1.y;
        d[4]=f2.x; d[5]=f2.y; d[6]=f3.x; d[7]=f3.y;
    }
    const float* xp = x + (size_t)n*64*HW + (size_t)h*Wd + w0;
    for(int i=t;i<512;i+=256){
        int c=i>>3, grp=(i&7)*4;
        *(float4*)&vs[(192+c)*PAD+grp] = *(const float4*)&xp[(size_t)c*HW+grp];
    }
    if(t<32){
        int w = w0 + t;
        int rp5 = ((h&31)*32 + (w&31))*P5 + (h>>5)*5 + (w>>5);
        q5s[t] = rp5 & 1023; cp05s[t] = rp5 >> 10;
        int R[2], C[2];
        int nr = cover3(h, R), nc = cover3(w, C);
        int ns = nr*nc;
        nsegS[t] = ns;
        icntS[t] = 1.f/(float)ns;
        #pragma unroll
        for(int s=0;s<4;s++){
            int ss = (s<ns) ? s : 0;
            int ph = R[ss/nc], pw = C[ss%nc];
            int rp3 = ((h-53*ph)*54 + (w-53*pw))*P3 + ph*3 + pw;
            cp03s[s][t] = rp3 / KHKW3;
            q3s[s][t]   = rp3 % KHKW3;
        }
    }
    __syncthreads();

    // stage sf3/sf5 tables + win1 s-field
    for(int i=t;i<1152;i+=256){
        int bp = i>>7, sp = i&127, s = sp>>5, pix = sp&31;
        sm3[s*288 + pix*9 + bp] = g_sf3[n*A3 + bp*KHKW3 + q3s[s][pix]];
    }
    for(int i=t;i<800;i+=256){
        int bp = i>>5, pix = i&31;
        sm5[pix*25 + bp] = g_sf5[n*25600 + (bp<<10) + q5s[pix]];
    }
    if(t>=224){   // last warp computes s1 (vs rows 0..63 already in smem)
        int pix = t-224;
        float sd = g_beff[n];
        const float* ve = &g_veff[n*64];
        #pragma unroll
        for(int c=0;c<64;c++) sd += ve[c]*vs[c*PAD+pix];
        s1s[pix] = sigf(sd);
    }
    __syncthreads();

    // multiplier (all table lookups in smem; gt is lane-broadcast from L1)
    for(int i=t;i<NO*32;i+=256){
        int k=i>>5, pix=i&31, win=k>>6, ci=k&63;
        float m;
        if(win==0){
            m = g_gt[n*64+ci] + s1s[pix];
        } else if(win==2){
            int cpv = cp05s[pix] + 25*ci;
            int bp = cpv>>6, cp = cpv&63;
            m = g_gt[(160+n*25+bp)*64+cp] + sm5[pix*25+bp];
        } else {
            m = 0.f;
            int ns = nsegS[pix];
            #pragma unroll
            for(int s=0;s<4;s++){
                if(s>=ns) break;
                int cpv = cp03s[s][pix] + 9*ci;
                int bp = cpv>>6, cp = cpv&63;
                m += g_gt[(16+n*9+bp)*64+cp] + sm3[s*288+pix*9+bp];
            }
            m *= icntS[pix];
        }
        vs[k*PAD+pix] *= (1.f + m);
    }
    __syncthreads();

    // GEMM: out[64ob][32px] = Wall[256k][64ob]^T @ vs[256k][32px]
    int pxp = t&15, px = pxp*2;
    int obg = t>>4, ob0 = obg*4;

    u64 acc0 = pk2(g_vb[ob0  ], g_vb[ob0  ]);
    u64 acc1 = pk2(g_vb[ob0+1], g_vb[ob0+1]);
    u64 acc2 = pk2(g_vb[ob0+2], g_vb[ob0+2]);
    u64 acc3 = pk2(g_vb[ob0+3], g_vb[ob0+3]);

    #pragma unroll 4
    for(int k=0;k<256;k++){
        u64 dv = *(const u64*)&vs[k*PAD+px];
        float4 wv = __ldg((const float4*)&g_Wall[k*64 + ob0]);
        fma2(acc0, pk2(wv.x,wv.x), dv);
        fma2(acc1, pk2(wv.y,wv.y), dv);
        fma2(acc2, pk2(wv.z,wv.z), dv);
        fma2(acc3, pk2(wv.w,wv.w), dv);
    }

    float* og = out + (size_t)n*64*HW + (size_t)h*Wd + w0 + px;
    float2 r0=up2(acc0), r1=up2(acc1), r2=up2(acc2), r3=up2(acc3);
    *(float2*)&og[(size_t)(ob0  )*HW] = r0;
    *(float2*)&og[(size_t)(ob0+1)*HW] = r1;
    *(float2*)&og[(size_t)(ob0+2)*HW] = r2;
    *(float2*)&og[(size_t)(ob0+3)*HW] = r3;
}

// ================ launch ================
extern "C" void kernel_launch(void* const* d_in, const int* in_sizes, int n_in,
                              void* d_out, int out_size){
    const float* x      = (const float*)d_in[0];
    const float* exp_w  = (const float*)d_in[1];
    const float* exp_b  = (const float*)d_in[2];
    const float* res_w  = (const float*)d_in[3];
    const float* res_b  = (const float*)d_in[4];
    const float* fus_w  = (const float*)d_in[5];
    const float* fus_b  = (const float*)d_in[6];
    const float* chwv_w = (const float*)d_in[7];
    const float* chwv_b = (const float*)d_in[8];
    const float* chwq_w = (const float*)d_in[9];
    const float* chwq_b = (const float*)d_in[10];
    const float* chwz_w = (const float*)d_in[11];
    const float* chwz_b = (const float*)d_in[12];
    const float* ln_g   = (const float*)d_in[13];
    const float* ln_b   = (const float*)d_in[14];
    const float* spwv_w = (const float*)d_in[15];
    const float* spwv_b = (const float*)d_in[16];
    const float* spwq_w = (const float*)d_in[17];
    const float* spwq_b = (const float*)d_in[18];
    float* out = (float*)d_out;

    __half *g_u3_p, *g_u5_p;
    float *g_sf3_p, *g_sf5_p;
    cudaGetSymbolAddress((void**)&g_u3_p, g_u3);
    cudaGetSymbolAddress((void**)&g_u5_p, g_u5);
    cudaGetSymbolAddress((void**)&g_sf3_p, g_sf3);
    cudaGetSymbolAddress((void**)&g_sf5_p, g_sf5);

    k_zero<<<(NPI*64+255)/256, 256>>>();
    k_wprep<<<1, 256>>>(exp_w, res_w, res_b, fus_w, fus_b);

    dim3 grid(Wd/32, Hh, NIMG);
    k1<<<grid, 256>>>(x, exp_b, chwq_w, chwq_b);

    k2_5<<<dim3(32,NIMG), 256>>>();
    k2_3<<<dim3(54,NIMG), 256>>>();

    k_stats<<<dim3(23,  9, NIMG), 256>>>(g_u3_p, KHKW3,(size_t)U3IMG, 16,  chwq_w, chwq_b);
    k_stats<<<dim3(8,  25, NIMG), 256>>>(g_u5_p, KHKW5,(size_t)U5IMG, 160, chwq_w, chwq_b);

    k4<<<NPI, 64>>>(chwv_w, chwv_b, chwz_w, chwz_b, ln_g, ln_b,
                    spwq_w, spwq_b, spwv_w, spwv_b);

    k_sfield<<<dim3(23,  9, NIMG), 256>>>(g_u3_p, KHKW3,(size_t)U3IMG, 16,  g_sf3_p);
    k_sfield<<<dim3(8,  25, NIMG), 256>>>(g_u5_p, KHKW5,(size_t)U5IMG, 160, g_sf5_p);

    k6<<<grid, 256>>>(x, out);
}

// round 9
// speedup vs baseline: 1.5122x; 1.5122x over previous
#include <cuda_runtime.h>
#include <cuda_fp16.h>
#include <math.h>

typedef unsigned long long u64;

#define NIMG 16
#define NO   192
#define Hh   160
#define Wd   160
#define HW   25600
#define PAD  36

#define KHKW3 2916
#define P3    9
#define A3    26244
#define U3IMG 1679616
#define KHKW5 1024
#define P5    25
#define A5    25600
#define U5IMG 1638400
#define NPI   560

// ---------------- scratch ----------------
__device__ __align__(16) __half g_ex[(size_t)NIMG*NO*HW];
__device__ __align__(16) __half g_u3[(size_t)NIMG*U3IMG];
__device__ __align__(16) __half g_u5[(size_t)NIMG*U5IMG];
__device__ __align__(16) float g_sf3[NIMG*P3*KHKW3];
__device__ __align__(16) float g_sf5[NIMG*P5*KHKW5];
__device__ float g_Z[NPI], g_S[NPI*64], g_Pm[NPI*64];
__device__ float g_gt[NPI*64], g_veff[NPI*64], g_beff[NPI];
__device__ __align__(16) float g_Wall[256*64];   // rows 0..191: fus@res [k][o]; 192..255: fus^T [c][o]
__device__ __align__(16) uint4 g_WhA4[4*16*32];  // HMMA A-fragments [mt][kt][lane]
__device__ float g_vb[64];
__device__ __align__(16) float g_expWt[64*NO];   // [c][o]

// ---------------- helpers ----------------
__device__ __forceinline__ u64 pk2(float lo, float hi){
    u64 r; asm("mov.b64 %0,{%1,%2};":"=l"(r):"f"(lo),"f"(hi)); return r;
}
__device__ __forceinline__ void fma2(u64 &d, u64 a, u64 b){
    asm("fma.rn.f32x2 %0,%1,%2,%3;":"=l"(d):"l"(a),"l"(b),"l"(d));
}
__device__ __forceinline__ float2 up2(u64 v){
    float2 f; asm("mov.b64 {%0,%1},%2;":"=f"(f.x),"=f"(f.y):"l"(v)); return f;
}
__device__ __forceinline__ float sigf(float x){ return 1.f/(1.f+expf(-x)); }
__device__ __forceinline__ int cover3(int h, int* r){
    int n=0;
    #pragma unroll
    for(int i=0;i<3;i++){ int lo=53*i; if(h>=lo && h<=lo+53) r[n++]=i; }
    return n;
}
__device__ __forceinline__ unsigned h2pack(float a, float b){
    __half2 h = __floats2half2_rn(a,b);
    return *(unsigned*)&h;
}

#define MMA16816(c0,c1,c2,c3,a,b0,b1) \
    asm volatile("mma.sync.aligned.m16n8k16.row.col.f32.f16.f16.f32 " \
        "{%0,%1,%2,%3},{%4,%5,%6,%7},{%8,%9},{%0,%1,%2,%3};" \
        : "+f"(c0),"+f"(c1),"+f"(c2),"+f"(c3) \
        : "r"((a).x),"r"((a).y),"r"((a).z),"r"((a).w),"r"(b0),"r"(b1))

// ================ K0a: zero accumulators ================
__global__ void k_zero(){
    int i = blockIdx.x*256 + threadIdx.x;
    if(i < NPI) g_Z[i]=0.f;
    if(i < NPI*64){ g_S[i]=0.f; g_Pm[i]=0.f; }
}

// ================ K0b: weight prep ================
__global__ void k_wprep(const float* __restrict__ exp_w, const float* __restrict__ res_w,
                        const float* __restrict__ res_b, const float* __restrict__ fus_w,
                        const float* __restrict__ fus_b){
    int t = threadIdx.x;
    for(int i=t;i<64*NO;i+=256){ int c=i/NO, o=i%NO; g_expWt[i]=exp_w[o*64+c]; }
    for(int i=t;i<NO*64;i+=256){
        int k=i/64, o=i%64; float s=0.f;
        for(int c=0;c<64;c++) s += fus_w[o*64+c]*res_w[c*NO+k];
        g_Wall[i]=s;
    }
    for(int i=t;i<64*64;i+=256){ int c=i/64, o=i%64; g_Wall[(192+c)*64+o]=fus_w[o*64+c]; }
    for(int o=t;o<64;o+=256){
        float s=fus_b[o];
        for(int c=0;c<64;c++) s += fus_w[o*64+c]*res_b[c];
        g_vb[o]=s;
    }
    __syncthreads();
    // HMMA A-fragments from g_Wall: A[m=ob][k], m16n8k16 canonical per-lane layout
    for(int i=t;i<2048;i+=256){
        int mt = i>>9, kt = (i>>5)&15, lane = i&31;
        int g = lane>>2, tig = lane&3;
        int k0 = kt*16, ob0 = mt*16;
        const float* W = g_Wall;
        unsigned r0 = h2pack(W[(k0+tig*2)*64+ob0+g],     W[(k0+tig*2+1)*64+ob0+g]);
        unsigned r1 = h2pack(W[(k0+tig*2)*64+ob0+g+8],   W[(k0+tig*2+1)*64+ob0+g+8]);
        unsigned r2 = h2pack(W[(k0+tig*2+8)*64+ob0+g],   W[(k0+tig*2+9)*64+ob0+g]);
        unsigned r3 = h2pack(W[(k0+tig*2+8)*64+ob0+g+8], W[(k0+tig*2+9)*64+ob0+g+8]);
        g_WhA4[i] = make_uint4(r0,r1,r2,r3);
    }
}

// ================ K1: ex = Wexp @ x + fused win1 stats (R6) ================
__global__ void __launch_bounds__(256) k1(const float* __restrict__ x,
                                          const float* __restrict__ exp_b,
                                          const float* __restrict__ wq,
                                          const float* __restrict__ wqb){
    __shared__ __align__(16) float xs[64*PAD];
    __shared__ float exs0[64*33];
    __shared__ float es[32];
    int t = threadIdx.x;
    int wt = blockIdx.x, h = blockIdx.y, n = blockIdx.z;
    int w0 = wt*32;

    const float* xp = x + (size_t)n*64*HW + (size_t)h*Wd + w0;
    for(int i=t;i<512;i+=256){
        int c=i>>3, grp=(i&7)*4;
        *(float4*)&xs[c*PAD+grp] = *(const float4*)&xp[(size_t)c*HW+grp];
    }
    __syncthreads();

    int ob = t&63, pg = t>>6, pb = pg*8;
    u64 acc[3][4];
    #pragma unroll
    for(int a=0;a<3;a++)
        #pragma unroll
        for(int j=0;j<4;j++) acc[a][j]=0ull;
    for(int c=0;c<64;c++){
        u64 xv[4];
        #pragma unroll
        for(int j=0;j<4;j++) xv[j]=*(const u64*)&xs[c*PAD+pb+j*2];
        #pragma unroll
        for(int a=0;a<3;a++){
            float w = g_expWt[c*NO + ob + a*64];
            u64 wp = pk2(w,w);
            #pragma unroll
            for(int j=0;j<4;j++) fma2(acc[a][j], wp, xv[j]);
        }
    }
    __half* exg = g_ex + (size_t)n*NO*HW + (size_t)h*Wd + w0;
    #pragma unroll
    for(int a=0;a<3;a++){
        float b = exp_b[ob+a*64];
        float2 v0=up2(acc[a][0]), v1=up2(acc[a][1]), v2=up2(acc[a][2]), v3=up2(acc[a][3]);
        if(a==0){
            float* d = &exs0[ob*33 + pb];
            d[0]=v0.x+b; d[1]=v0.y+b; d[2]=v1.x+b; d[3]=v1.y+b;
            d[4]=v2.x+b; d[5]=v2.y+b; d[6]=v3.x+b; d[7]=v3.y+b;
        }
        __half2 h0=__floats2half2_rn(v0.x+b, v0.y+b);
        __half2 h1=__floats2half2_rn(v1.x+b, v1.y+b);
        __half2 h2=__floats2half2_rn(v2.x+b, v2.y+b);
        __half2 h3=__floats2half2_rn(v3.x+b, v3.y+b);
        uint4 pk;
        pk.x=*(unsigned*)&h0; pk.y=*(unsigned*)&h1;
        pk.z=*(unsigned*)&h2; pk.w=*(unsigned*)&h3;
        *(uint4*)&exg[(size_t)(ob+a*64)*HW + pb] = pk;
    }
    __syncthreads();

    if(t<32){
        float qd = wqb[0];
        #pragma unroll
        for(int c=0;c<64;c++) qd += wq[c]*exs0[c*33+t];
        float e = expf(qd);
        es[t]=e;
        float z=e;
        for(int off=16;off;off>>=1) z += __shfl_xor_sync(0xffffffffu,z,off);
        if(t==0) atomicAdd(&g_Z[n], z);
    }
    __syncthreads();
    if(t<64){
        float Ps=0.f, Ss=0.f;
        #pragma unroll
        for(int px=0;px<32;px++){ float v=exs0[t*33+px]; Ps+=v; Ss+=v*es[px]; }
        atomicAdd(&g_S[n*64+t], Ss);
        atomicAdd(&g_Pm[n*64+t], Ps);
    }
}

// ================ K2: repack into unfold order (warp-per-ci, fp16) ================
__global__ void __launch_bounds__(256) k2_5(){
    __shared__ __align__(16) __half rb[8][800];
    int y = blockIdx.x, n = blockIdx.y;
    int wp = threadIdx.x >> 5, lane = threadIdx.x & 31;
    for(int cit=0; cit<8; cit++){
        int ci = cit*8 + wp;
        const __half* src = g_ex + (size_t)n*NO*HW + (size_t)(128+ci)*HW;
        #pragma unroll
        for(int ph=0; ph<5; ph++){
            const __half2* row2 = (const __half2*)(src + (size_t)(ph*32+y)*Wd);
            #pragma unroll
            for(int it=0; it<3; it++){
                int idx = lane + it*32;
                if(idx<80){
                    __half2 v = row2[idx];
                    int w = idx*2, pw = w>>5, xx = w&31;
                    rb[wp][xx*25 + ph*5 + pw]     = __low2half(v);
                    rb[wp][(xx+1)*25 + ph*5 + pw] = __high2half(v);
                }
            }
        }
        __syncwarp();
        uint4* dst = (uint4*)(g_u5 + (size_t)n*U5IMG + (size_t)(ci*1024 + y*32)*25);
        const uint4* s = (const uint4*)rb[wp];
        #pragma unroll
        for(int it=0; it<4; it++){
            int k = lane + it*32;
            if(k < 100) dst[k] = s[k];
        }
        __syncwarp();
    }
}
__global__ void __launch_bounds__(256) k2_3(){
    __shared__ __align__(16) __half rb[8][488];
    int yy = blockIdx.x, n = blockIdx.y;
    int wp = threadIdx.x >> 5, lane = threadIdx.x & 31;
    for(int cit=0; cit<8; cit++){
        int ci = cit*8 + wp;
        const __half* src = g_ex + (size_t)n*NO*HW + (size_t)(64+ci)*HW;
        #pragma unroll
        for(int ph=0; ph<3; ph++){
            const __half2* row2 = (const __half2*)(src + (size_t)(53*ph+yy)*Wd);
            #pragma unroll
            for(int it=0; it<3; it++){
                int idx = lane + it*32;
                if(idx<80){
                    __half2 v = row2[idx];
                    int w0_ = idx*2;
                    __half hv[2] = {__low2half(v), __high2half(v)};
                    #pragma unroll
                    for(int hh=0; hh<2; hh++){
                        int w = w0_ + hh;
                        #pragma unroll
                        for(int pw=0; pw<3; pw++){
                            int xx = w - 53*pw;
                            if(xx>=0 && xx<54) rb[wp][xx*9 + ph*3 + pw] = hv[hh];
                        }
                    }
                }
            }
        }
        __syncwarp();
        unsigned* dst = (unsigned*)(g_u3 + (size_t)n*U3IMG + (size_t)ci*A3 + (size_t)yy*486);
        const unsigned* s = (const unsigned*)rb[wp];
        #pragma unroll
        for(int it=0; it<8; it++){
            int k = lane + it*32;
            if(k < 243) dst[k] = s[k];
        }
        __syncwarp();
    }
}

// ================ K3: stats (fp16 smem, q-tile 128) ================
__global__ void __launch_bounds__(256) k_stats(const __half* __restrict__ ub, int khkw,
                                               size_t imgstride, int piBase,
                                               const float* __restrict__ wq,
                                               const float* __restrict__ wqb){
    __shared__ __half Vs[64*130];
    __shared__ float part[4*128];
    __shared__ float es[128];
    int q0 = blockIdx.x*128, bp = blockIdx.y, n = blockIdx.z;
    int t = threadIdx.x;
    const __half* base = ub + (size_t)n*imgstride + (size_t)bp*64*khkw + q0;
    int qlim = khkw - q0; if(qlim>128) qlim=128;

    for(int i=t;i<4096;i+=256){
        int c=i>>6, j2=i&63;
        unsigned v = 0;
        if(j2*2 < qlim) v = *(const unsigned*)&base[(size_t)c*khkw + j2*2];
        *(unsigned*)&Vs[c*130 + j2*2] = v;
    }
    __syncthreads();
    {
        int j2=t&63, cg=t>>6;
        float sx=0.f, sy=0.f;
        #pragma unroll 8
        for(int cc=cg*16; cc<cg*16+16; cc++){
            float2 f = __half22float2(*(const __half2*)&Vs[cc*130 + j2*2]);
            float w = wq[cc];
            sx += w*f.x; sy += w*f.y;
        }
        part[cg*128 + j2*2]   = sx;
        part[cg*128 + j2*2+1] = sy;
    }
    __syncthreads();
    int pi = piBase + n*gridDim.y + bp;
    if(t<128){
        float qd = part[t]+part[128+t]+part[256+t]+part[384+t] + wqb[0];
        float e = (t<qlim) ? expf(qd) : 0.f;
        es[t]=e;
        float z=e;
        for(int off=16;off;off>>=1) z += __shfl_xor_sync(0xffffffffu,z,off);
        if((t&31)==0) atomicAdd(&g_Z[pi], z);
    }
    __syncthreads();
    {
        int c=t&63, jg=t>>6;
        float ss=0.f, pm=0.f;
        #pragma unroll 8
        for(int j2=jg*16; j2<jg*16+16; j2++){
            float2 f = __half22float2(*(const __half2*)&Vs[c*130 + j2*2]);
            ss += f.x*es[2*j2] + f.y*es[2*j2+1];
            pm += f.x + f.y;
        }
        atomicAdd(&g_S[pi*64+c], ss);
        atomicAdd(&g_Pm[pi*64+c], pm);
    }
}

// ================ K4: per-pseudo-image finalize ================
__global__ void __launch_bounds__(64) k4(const float* __restrict__ chwv_w, const float* __restrict__ chwv_b,
                                         const float* __restrict__ chwz_w, const float* __restrict__ chwz_b,
                                         const float* __restrict__ ln_g,  const float* __restrict__ ln_b,
                                         const float* __restrict__ spwq_w,const float* __restrict__ spwq_b,
                                         const float* __restrict__ spwv_w,const float* __restrict__ spwv_b){
    int p = blockIdx.x, t = threadIdx.x;
    float hw = (p<16) ? 25600.f : ((p<160) ? 2916.f : 1024.f);
    __shared__ float xbar[64], pmean[64], wz[32], red[64], swq[32];

    float Zinv = 1.f/g_Z[p];
    xbar[t]  = g_S[p*64+t]*Zinv;
    pmean[t] = g_Pm[p*64+t]/hw;
    __syncthreads();

    if(t<32){
        float s = chwv_b[t];
        for(int c=0;c<64;c++) s += chwv_w[t*64+c]*xbar[c];
        wz[t]=s;
    }
    __syncthreads();

    float z = chwz_b[t];
    for(int j=0;j<32;j++) z += chwz_w[t*32+j]*wz[j];

    red[t]=z; __syncthreads();
    for(int s=32;s>0;s>>=1){ if(t<s) red[t]+=red[t+s]; __syncthreads(); }
    float mu = red[0]*(1.f/64.f); __syncthreads();
    float d = z-mu;
    red[t]=d*d; __syncthreads();
    for(int s=32;s>0;s>>=1){ if(t<s) red[t]+=red[t+s]; __syncthreads(); }
    float var = red[0]*(1.f/64.f);

    float zn = d*rsqrtf(var+1e-5f)*ln_g[t] + ln_b[t];
    g_gt[p*64+t] = sigf(zn);
    __syncthreads();

    if(t<32){
        float s = spwq_b[t];
        for(int c=0;c<64;c++) s += spwq_w[t*64+c]*pmean[c];
        float m=s;
        for(int off=16;off;off>>=1) m=fmaxf(m,__shfl_xor_sync(0xffffffffu,m,off));
        float e=expf(s-m), sum=e;
        for(int off=16;off;off>>=1) sum+=__shfl_xor_sync(0xffffffffu,sum,off);
        swq[t]=e/sum;
    }
    __syncthreads();

    float v=0.f;
    for(int j=0;j<32;j++) v += swq[j]*spwv_w[j*64+t];
    g_veff[p*64+t]=v;
    if(t==0){
        float b=0.f;
        for(int j=0;j<32;j++) b += swq[j]*spwv_b[j];
        g_beff[p]=b;
    }
}

// ================ K5: s-field (fp16 smem, q-tile 128) ================
__global__ void __launch_bounds__(256) k_sfield(const __half* __restrict__ ub, int khkw,
                                                size_t imgstride, int piBase,
                                                float* __restrict__ sf){
    __shared__ __half Vs[64*130];
    __shared__ float part[4*128];
    __shared__ float ve[64];
    int q0 = blockIdx.x*128, bp = blockIdx.y, n = blockIdx.z;
    int t = threadIdx.x;
    int pi = piBase + n*gridDim.y + bp;
    const __half* base = ub + (size_t)n*imgstride + (size_t)bp*64*khkw + q0;
    int qlim = khkw - q0; if(qlim>128) qlim=128;

    if(t<64) ve[t]=g_veff[pi*64+t];
    for(int i=t;i<4096;i+=256){
        int c=i>>6, j2=i&63;
        unsigned v = 0;
        if(j2*2 < qlim) v = *(const unsigned*)&base[(size_t)c*khkw + j2*2];
        *(unsigned*)&Vs[c*130 + j2*2] = v;
    }
    __syncthreads();
    {
        int j2=t&63, cg=t>>6;
        float sx=0.f, sy=0.f;
        #pragma unroll 8
        for(int cc=cg*16; cc<cg*16+16; cc++){
            float2 f = __half22float2(*(const __half2*)&Vs[cc*130 + j2*2]);
            float w = ve[cc];
            sx += w*f.x; sy += w*f.y;
        }
        part[cg*128 + j2*2]   = sx;
        part[cg*128 + j2*2+1] = sy;
    }
    __syncthreads();
    if(t<128 && t<qlim){
        float sd = part[t]+part[128+t]+part[256+t]+part[384+t] + g_beff[pi];
        sf[(size_t)n*(gridDim.y*khkw) + (size_t)bp*khkw + q0 + t] = sigf(sd);
    }
}

// ================ K6: s1 + div-free multiplier + HMMA GEMM ================
__global__ void __launch_bounds__(256) k6(const float* __restrict__ x, float* __restrict__ out){
    __shared__ __align__(16) float vs[192*PAD];      // ex tile fp32
    __shared__ __align__(16) __half vsh[32*264];     // GEMM input, px-major, pitch 264
    __shared__ float s1s[32], icntS[32];
    __shared__ int q5s[32], cp05s[32];
    __shared__ int q3s[4][32], cp03s[4][32];
    __shared__ int nsegS[32];

    int t = threadIdx.x;
    int wt = blockIdx.x, h = blockIdx.y, n = blockIdx.z;
    int w0 = wt*32;

    const __half* exg = g_ex + (size_t)n*NO*HW + (size_t)h*Wd + w0;
    for(int i=t;i<768;i+=256){
        int k=i>>2, q=(i&3)*8;
        uint4 raw = *(const uint4*)&exg[(size_t)k*HW + q];
        __half2* hp = (__half2*)&raw;
        float2 f0=__half22float2(hp[0]), f1=__half22float2(hp[1]);
        float2 f2=__half22float2(hp[2]), f3=__half22float2(hp[3]);
        float* d = &vs[k*PAD+q];
        d[0]=f0.x; d[1]=f0.y; d[2]=f1.x; d[3]=f1.y;
        d[4]=f2.x; d[5]=f2.y; d[6]=f3.x; d[7]=f3.y;
    }
    if(t<32){
        int w = w0 + t;
        int rp5 = ((h&31)*32 + (w&31))*P5 + (h>>5)*5 + (w>>5);
        q5s[t] = rp5 & 1023; cp05s[t] = rp5 >> 10;
        int R[2], C[2];
        int nr = cover3(h, R), nc = cover3(w, C);
        nsegS[t] = nr*nc;
        icntS[t] = 1.f/(float)(nr*nc);
        for(int ri=0;ri<nr;ri++)
            for(int cj=0;cj<nc;cj++){
                int ph=R[ri], pw=C[cj];
                int rp3 = ((h-53*ph)*54 + (w-53*pw))*P3 + ph*3 + pw;
                int s = ri*nc + cj;
                cp03s[s][t] = rp3 / KHKW3;
                q3s[s][t]   = rp3 % KHKW3;
            }
    }
    __syncthreads();

    // x -> vsh rows 192..255 (fp16, transposed layout)
    const float* xp = x + (size_t)n*64*HW + (size_t)h*Wd + w0;
    for(int i=t;i<2048;i+=256){
        int c=i>>5, px=i&31;
        vsh[px*264 + 192 + c] = __float2half(xp[(size_t)c*HW+px]);
    }
    // win1 s-field from raw chunk0
    if(t<32){
        float sd = g_beff[n];
        const float* ve = &g_veff[n*64];
        #pragma unroll
        for(int c=0;c<64;c++) sd += ve[c]*vs[c*PAD+t];
        s1s[t] = sigf(sd);
    }
    __syncthreads();

    // multiplier (div-free) -> vsh rows 0..191
    for(int i=t;i<NO*32;i+=256){
        int k=i>>5, pix=i&31, win=k>>6, ci=k&63;
        float m;
        if(win==0){
            m = g_gt[n*64+ci] + s1s[pix];
        } else if(win==2){
            int cpv = cp05s[pix] + 25*ci;
            int bp = cpv>>6, cp = cpv&63;
            m = g_gt[(160+n*25+bp)*64+cp] + g_sf5[n*25600 + (bp<<10) + q5s[pix]];
        } else {
            m = 0.f;
            int ns = nsegS[pix];
            #pragma unroll
            for(int s=0;s<4;s++){
                if(s>=ns) break;
                int cpv = cp03s[s][pix] + 9*ci;
                int bp = cpv>>6, cp = cpv&63;
                m += g_gt[(16+n*9+bp)*64+cp] + g_sf3[n*A3 + bp*KHKW3 + q3s[s][pix]];
            }
            m *= icntS[pix];
        }
        vsh[pix*264 + k] = __float2half(vs[k*PAD+pix]*(1.f + m));
    }
    __syncthreads();

    // HMMA GEMM: out[64ob][32px] = Wall^T[64][256] @ vsh[256][32]
    int lane = t&31, w = t>>5;
    int g = lane>>2, tig = lane&3;
    int mt = w&3, nt0 = (w>>2)*2, nt1 = nt0+1;
    int ob0 = mt*16;

    float vb0 = __ldg(&g_vb[ob0+g]), vb1 = __ldg(&g_vb[ob0+g+8]);
    float c00=vb0, c01=vb0, c02=vb1, c03=vb1;
    float c10=vb0, c11=vb0, c12=vb1, c13=vb1;

    const uint4* wa = g_WhA4 + mt*512 + lane;
    const __half* b0base = &vsh[(nt0*8+g)*264 + tig*2];
    const __half* b1base = &vsh[(nt1*8+g)*264 + tig*2];

    #pragma unroll
    for(int kt=0;kt<16;kt++){
        uint4 a = __ldg(&wa[kt*32]);
        int k0 = kt*16;
        unsigned p00 = *(const unsigned*)&b0base[k0];
        unsigned p01 = *(const unsigned*)&b0base[k0+8];
        MMA16816(c00,c01,c02,c03, a, p00,p01);
        unsigned p10 = *(const unsigned*)&b1base[k0];
        unsigned p11 = *(const unsigned*)&b1base[k0+8];
        MMA16816(c10,c11,c12,c13, a, p10,p11);
    }

    float* og = out + (size_t)n*64*HW + (size_t)h*Wd + w0;
    int px0 = nt0*8 + tig*2, px1 = nt1*8 + tig*2;
    *(float2*)&og[(size_t)(ob0+g  )*HW + px0] = make_float2(c00,c01);
    *(float2*)&og[(size_t)(ob0+g+8)*HW + px0] = make_float2(c02,c03);
    *(float2*)&og[(size_t)(ob0+g  )*HW + px1] = make_float2(c10,c11);
    *(float2*)&og[(size_t)(ob0+g+8)*HW + px1] = make_float2(c12,c13);
}

// ================ launch ================
extern "C" void kernel_launch(void* const* d_in, const int* in_sizes, int n_in,
                              void* d_out, int out_size){
    const float* x      = (const float*)d_in[0];
    const float* exp_w  = (const float*)d_in[1];
    const float* exp_b  = (const float*)d_in[2];
    const float* res_w  = (const float*)d_in[3];
    const float* res_b  = (const float*)d_in[4];
    const float* fus_w  = (const float*)d_in[5];
    const float* fus_b  = (const float*)d_in[6];
    const float* chwv_w = (const float*)d_in[7];
    const float* chwv_b = (const float*)d_in[8];
    const float* chwq_w = (const float*)d_in[9];
    const float* chwq_b = (const float*)d_in[10];
    const float* chwz_w = (const float*)d_in[11];
    const float* chwz_b = (const float*)d_in[12];
    const float* ln_g   = (const float*)d_in[13];
    const float* ln_b   = (const float*)d_in[14];
    const float* spwv_w = (const float*)d_in[15];
    const float* spwv_b = (const float*)d_in[16];
    const float* spwq_w = (const float*)d_in[17];
    const float* spwq_b = (const float*)d_in[18];
    float* out = (float*)d_out;

    __half *g_u3_p, *g_u5_p;
    float *g_sf3_p, *g_sf5_p;
    cudaGetSymbolAddress((void**)&g_u3_p, g_u3);
    cudaGetSymbolAddress((void**)&g_u5_p, g_u5);
    cudaGetSymbolAddress((void**)&g_sf3_p, g_sf3);
    cudaGetSymbolAddress((void**)&g_sf5_p, g_sf5);

    k_zero<<<(NPI*64+255)/256, 256>>>();
    k_wprep<<<1, 256>>>(exp_w, res_w, res_b, fus_w, fus_b);

    dim3 grid(Wd/32, Hh, NIMG);
    k1<<<grid, 256>>>(x, exp_b, chwq_w, chwq_b);

    k2_5<<<dim3(32,NIMG), 256>>>();
    k2_3<<<dim3(54,NIMG), 256>>>();

    k_stats<<<dim3(23,  9, NIMG), 256>>>(g_u3_p, KHKW3,(size_t)U3IMG, 16,  chwq_w, chwq_b);
    k_stats<<<dim3(8,  25, NIMG), 256>>>(g_u5_p, KHKW5,(size_t)U5IMG, 160, chwq_w, chwq_b);

    k4<<<NPI, 64>>>(chwv_w, chwv_b, chwz_w, chwz_b, ln_g, ln_b,
                    spwq_w, spwq_b, spwv_w, spwv_b);

    k_sfield<<<dim3(23,  9, NIMG), 256>>>(g_u3_p, KHKW3,(size_t)U3IMG, 16,  g_sf3_p);
    k_sfield<<<dim3(8,  25, NIMG), 256>>>(g_u5_p, KHKW5,(size_t)U5IMG, 160, g_sf5_p);

    k6<<<grid, 256>>>(x, out);
}

// round 10
// speedup vs baseline: 2.0306x; 1.3428x over previous
#include <cuda_runtime.h>
#include <cuda_fp16.h>
#include <math.h>

typedef unsigned long long u64;

#define NIMG 16
#define NO   192
#define Hh   160
#define Wd   160
#define HW   25600
#define PAD  36

#define KHKW3 2916
#define P3    9
#define A3    26244
#define U3IMG 1679616
#define KHKW5 1024
#define P5    25
#define A5    25600
#define U5IMG 1638400
#define NPI   560

// ---------------- scratch ----------------
__device__ __align__(16) __half g_ex[(size_t)NIMG*NO*HW];
__device__ __align__(16) __half g_u3[(size_t)NIMG*U3IMG];
__device__ __align__(16) __half g_u5[(size_t)NIMG*U5IMG];
__device__ __align__(16) float g_sf3[NIMG*P3*KHKW3];
__device__ __align__(16) float g_sf5[NIMG*P5*KHKW5];
__device__ float g_Z[NPI], g_S[NPI*64], g_Pm[NPI*64];
__device__ float g_gt[NPI*64], g_veff[NPI*64], g_beff[NPI];
__device__ __align__(16) float g_Wall[256*64];   // rows 0..191: fus@res [k][o]; 192..255: fus^T [c][o]
__device__ __align__(16) uint4 g_WhA4[4*16*32];  // K6 HMMA A-fragments [mt][kt][lane]
__device__ __align__(16) uint4 g_WK1A4[12*4*32]; // K1 HMMA A-fragments [mt][kt][lane]
__device__ float g_vb[64];
__device__ __align__(16) float g_expWt[64*NO];   // [c][o]

// ---------------- helpers ----------------
__device__ __forceinline__ float sigf(float x){ return 1.f/(1.f+expf(-x)); }
__device__ __forceinline__ int cover3(int h, int* r){
    int n=0;
    #pragma unroll
    for(int i=0;i<3;i++){ int lo=53*i; if(h>=lo && h<=lo+53) r[n++]=i; }
    return n;
}
__device__ __forceinline__ unsigned h2pack(float a, float b){
    __half2 h = __floats2half2_rn(a,b);
    return *(unsigned*)&h;
}

#define MMA16816(c0,c1,c2,c3,a,b0,b1) \
    asm volatile("mma.sync.aligned.m16n8k16.row.col.f32.f16.f16.f32 " \
        "{%0,%1,%2,%3},{%4,%5,%6,%7},{%8,%9},{%0,%1,%2,%3};" \
        : "+f"(c0),"+f"(c1),"+f"(c2),"+f"(c3) \
        : "r"((a).x),"r"((a).y),"r"((a).z),"r"((a).w),"r"(b0),"r"(b1))

// ================ K0a: zero accumulators ================
__global__ void k_zero(){
    int i = blockIdx.x*256 + threadIdx.x;
    if(i < NPI) g_Z[i]=0.f;
    if(i < NPI*64){ g_S[i]=0.f; g_Pm[i]=0.f; }
}

// ================ K0b: weight prep ================
__global__ void k_wprep(const float* __restrict__ exp_w, const float* __restrict__ res_w,
                        const float* __restrict__ res_b, const float* __restrict__ fus_w,
                        const float* __restrict__ fus_b){
    int t = threadIdx.x;
    for(int i=t;i<64*NO;i+=256){ int c=i/NO, o=i%NO; g_expWt[i]=exp_w[o*64+c]; }
    for(int i=t;i<NO*64;i+=256){
        int k=i/64, o=i%64; float s=0.f;
        for(int c=0;c<64;c++) s += fus_w[o*64+c]*res_w[c*NO+k];
        g_Wall[i]=s;
    }
    for(int i=t;i<64*64;i+=256){ int c=i/64, o=i%64; g_Wall[(192+c)*64+o]=fus_w[o*64+c]; }
    for(int o=t;o<64;o+=256){
        float s=fus_b[o];
        for(int c=0;c<64;c++) s += fus_w[o*64+c]*res_b[c];
        g_vb[o]=s;
    }
    __syncthreads();
    // K6 A-fragments from g_Wall [k][m], stride 64
    for(int i=t;i<2048;i+=256){
        int mt = i>>9, kt = (i>>5)&15, lane = i&31;
        int g = lane>>2, tig = lane&3;
        int k0 = kt*16, ob0 = mt*16;
        const float* W = g_Wall;
        unsigned r0 = h2pack(W[(k0+tig*2)*64+ob0+g],     W[(k0+tig*2+1)*64+ob0+g]);
        unsigned r1 = h2pack(W[(k0+tig*2)*64+ob0+g+8],   W[(k0+tig*2+1)*64+ob0+g+8]);
        unsigned r2 = h2pack(W[(k0+tig*2+8)*64+ob0+g],   W[(k0+tig*2+9)*64+ob0+g]);
        unsigned r3 = h2pack(W[(k0+tig*2+8)*64+ob0+g+8], W[(k0+tig*2+9)*64+ob0+g+8]);
        g_WhA4[i] = make_uint4(r0,r1,r2,r3);
    }
    // K1 A-fragments from g_expWt [k][m], stride NO
    for(int i=t;i<1536;i+=256){
        int mt = i>>7, kt = (i>>5)&3, lane = i&31;
        int g = lane>>2, tig = lane&3;
        int k0 = kt*16, ob0 = mt*16;
        const float* W = g_expWt;
        unsigned r0 = h2pack(W[(k0+tig*2)*NO+ob0+g],     W[(k0+tig*2+1)*NO+ob0+g]);
        unsigned r1 = h2pack(W[(k0+tig*2)*NO+ob0+g+8],   W[(k0+tig*2+1)*NO+ob0+g+8]);
        unsigned r2 = h2pack(W[(k0+tig*2+8)*NO+ob0+g],   W[(k0+tig*2+9)*NO+ob0+g]);
        unsigned r3 = h2pack(W[(k0+tig*2+8)*NO+ob0+g+8], W[(k0+tig*2+9)*NO+ob0+g+8]);
        g_WK1A4[i] = make_uint4(r0,r1,r2,r3);
    }
}

// ================ K1: HMMA ex = Wexp @ x + fused win1 stats ================
__global__ void __launch_bounds__(256) k1(const float* __restrict__ x,
                                          const float* __restrict__ exp_b,
                                          const float* __restrict__ wq,
                                          const float* __restrict__ wqb){
    __shared__ __align__(16) __half xh[32*72];     // [px][c], pitch 72 halves
    __shared__ __align__(16) __half exsh[192*40];  // [ob][px], pitch 40 halves
    __shared__ float es[32];
    int t = threadIdx.x;
    int wt = blockIdx.x, h = blockIdx.y, n = blockIdx.z;
    int w0 = wt*32;

    // load x tile, transpose to fp16 [px][c]
    const float* xp = x + (size_t)n*64*HW + (size_t)h*Wd + w0;
    for(int i=t;i<512;i+=256){
        int c=i>>3, p4=(i&7)*4;
        float4 v = *(const float4*)&xp[(size_t)c*HW + p4];
        xh[(p4  )*72 + c] = __float2half(v.x);
        xh[(p4+1)*72 + c] = __float2half(v.y);
        xh[(p4+2)*72 + c] = __float2half(v.z);
        xh[(p4+3)*72 + c] = __float2half(v.w);
    }
    __syncthreads();

    int lane = t&31, w = t>>5;
    int g = lane>>2, tig = lane&3;
    int mtb = (w&3)*3, nt0 = (w>>2)*2, nt1 = nt0+1;
    int px0 = nt0*8 + tig*2, px1 = nt1*8 + tig*2;

    const __half* b0base = &xh[(nt0*8+g)*72 + tig*2];
    const __half* b1base = &xh[(nt1*8+g)*72 + tig*2];
    unsigned bf0[8], bf1[8];
    #pragma unroll
    for(int kt=0;kt<4;kt++){
        bf0[kt*2  ] = *(const unsigned*)&b0base[kt*16];
        bf0[kt*2+1] = *(const unsigned*)&b0base[kt*16+8];
        bf1[kt*2  ] = *(const unsigned*)&b1base[kt*16];
        bf1[kt*2+1] = *(const unsigned*)&b1base[kt*16+8];
    }

    #pragma unroll
    for(int mi=0;mi<3;mi++){
        int mt = mtb+mi, ob0 = mt*16;
        float c00=0,c01=0,c02=0,c03=0, c10=0,c11=0,c12=0,c13=0;
        const uint4* wa = g_WK1A4 + mt*128 + lane;
        #pragma unroll
        for(int kt=0;kt<4;kt++){
            uint4 a = __ldg(&wa[kt*32]);
            MMA16816(c00,c01,c02,c03, a, bf0[kt*2],bf0[kt*2+1]);
            MMA16816(c10,c11,c12,c13, a, bf1[kt*2],bf1[kt*2+1]);
        }
        float b0 = __ldg(&exp_b[ob0+g]), b1 = __ldg(&exp_b[ob0+g+8]);
        *(unsigned*)&exsh[(ob0+g  )*40 + px0] = h2pack(c00+b0, c01+b0);
        *(unsigned*)&exsh[(ob0+g+8)*40 + px0] = h2pack(c02+b1, c03+b1);
        *(unsigned*)&exsh[(ob0+g  )*40 + px1] = h2pack(c10+b0, c11+b0);
        *(unsigned*)&exsh[(ob0+g+8)*40 + px1] = h2pack(c12+b1, c13+b1);
    }
    __syncthreads();

    // coalesced global store
    __half* exg = g_ex + (size_t)n*NO*HW + (size_t)h*Wd + w0;
    for(int i=t;i<768;i+=256){
        int r=i>>2, q=(i&3)*8;
        *(uint4*)&exg[(size_t)r*HW + q] = *(const uint4*)&exsh[r*40 + q];
    }

    // fused win1 stats from exsh rows 0..63
    if(t<32){
        float qd = wqb[0];
        #pragma unroll
        for(int c=0;c<64;c++) qd += wq[c]*__half2float(exsh[c*40+t]);
        float e = expf(qd);
        es[t]=e;
        float z=e;
        for(int off=16;off;off>>=1) z += __shfl_xor_sync(0xffffffffu,z,off);
        if(t==0) atomicAdd(&g_Z[n], z);
    }
    __syncthreads();
    if(t<64){
        float Ps=0.f, Ss=0.f;
        #pragma unroll
        for(int px=0;px<32;px++){ float v=__half2float(exsh[t*40+px]); Ps+=v; Ss+=v*es[px]; }
        atomicAdd(&g_S[n*64+t], Ss);
        atomicAdd(&g_Pm[n*64+t], Ps);
    }
}

// ================ K2: repack into unfold order (warp-per-ci, fp16) ================
__global__ void __launch_bounds__(256) k2_5(){
    __shared__ __align__(16) __half rb[8][800];
    int y = blockIdx.x, n = blockIdx.y;
    int wp = threadIdx.x >> 5, lane = threadIdx.x & 31;
    for(int cit=0; cit<8; cit++){
        int ci = cit*8 + wp;
        const __half* src = g_ex + (size_t)n*NO*HW + (size_t)(128+ci)*HW;
        #pragma unroll
        for(int ph=0; ph<5; ph++){
            const __half2* row2 = (const __half2*)(src + (size_t)(ph*32+y)*Wd);
            #pragma unroll
            for(int it=0; it<3; it++){
                int idx = lane + it*32;
                if(idx<80){
                    __half2 v = row2[idx];
                    int w = idx*2, pw = w>>5, xx = w&31;
                    rb[wp][xx*25 + ph*5 + pw]     = __low2half(v);
                    rb[wp][(xx+1)*25 + ph*5 + pw] = __high2half(v);
                }
            }
        }
        __syncwarp();
        uint4* dst = (uint4*)(g_u5 + (size_t)n*U5IMG + (size_t)(ci*1024 + y*32)*25);
        const uint4* s = (const uint4*)rb[wp];
        #pragma unroll
        for(int it=0; it<4; it++){
            int k = lane + it*32;
            if(k < 100) dst[k] = s[k];
        }
        __syncwarp();
    }
}
__global__ void __launch_bounds__(256) k2_3(){
    __shared__ __align__(16) __half rb[8][488];
    int yy = blockIdx.x, n = blockIdx.y;
    int wp = threadIdx.x >> 5, lane = threadIdx.x & 31;
    for(int cit=0; cit<8; cit++){
        int ci = cit*8 + wp;
        const __half* src = g_ex + (size_t)n*NO*HW + (size_t)(64+ci)*HW;
        #pragma unroll
        for(int ph=0; ph<3; ph++){
            const __half2* row2 = (const __half2*)(src + (size_t)(53*ph+yy)*Wd);
            #pragma unroll
            for(int it=0; it<3; it++){
                int idx = lane + it*32;
                if(idx<80){
                    __half2 v = row2[idx];
                    int w0_ = idx*2;
                    __half hv[2] = {__low2half(v), __high2half(v)};
                    #pragma unroll
                    for(int hh=0; hh<2; hh++){
                        int w = w0_ + hh;
                        #pragma unroll
                        for(int pw=0; pw<3; pw++){
                            int xx = w - 53*pw;
                            if(xx>=0 && xx<54) rb[wp][xx*9 + ph*3 + pw] = hv[hh];
                        }
                    }
                }
            }
        }
        __syncwarp();
        unsigned* dst = (unsigned*)(g_u3 + (size_t)n*U3IMG + (size_t)ci*A3 + (size_t)yy*486);
        const unsigned* s = (const unsigned*)rb[wp];
        #pragma unroll
        for(int it=0; it<8; it++){
            int k = lane + it*32;
            if(k < 243) dst[k] = s[k];
        }
        __syncwarp();
    }
}

// ================ K3: stats (fp16 smem, q-tile 128) ================
__global__ void __launch_bounds__(256) k_stats(const __half* __restrict__ ub, int khkw,
                                               size_t imgstride, int piBase,
                                               const float* __restrict__ wq,
                                               const float* __restrict__ wqb){
    __shared__ __half Vs[64*130];
    __shared__ float part[4*128];
    __shared__ float es[128];
    int q0 = blockIdx.x*128, bp = blockIdx.y, n = blockIdx.z;
    int t = threadIdx.x;
    const __half* base = ub + (size_t)n*imgstride + (size_t)bp*64*khkw + q0;
    int qlim = khkw - q0; if(qlim>128) qlim=128;

    for(int i=t;i<4096;i+=256){
        int c=i>>6, j2=i&63;
        unsigned v = 0;
        if(j2*2 < qlim) v = *(const unsigned*)&base[(size_t)c*khkw + j2*2];
        *(unsigned*)&Vs[c*130 + j2*2] = v;
    }
    __syncthreads();
    {
        int j2=t&63, cg=t>>6;
        float sx=0.f, sy=0.f;
        #pragma unroll 8
        for(int cc=cg*16; cc<cg*16+16; cc++){
            float2 f = __half22float2(*(const __half2*)&Vs[cc*130 + j2*2]);
            float w = wq[cc];
            sx += w*f.x; sy += w*f.y;
        }
        part[cg*128 + j2*2]   = sx;
        part[cg*128 + j2*2+1] = sy;
    }
    __syncthreads();
    int pi = piBase + n*gridDim.y + bp;
    if(t<128){
        float qd = part[t]+part[128+t]+part[256+t]+part[384+t] + wqb[0];
        float e = (t<qlim) ? expf(qd) : 0.f;
        es[t]=e;
        float z=e;
        for(int off=16;off;off>>=1) z += __shfl_xor_sync(0xffffffffu,z,off);
        if((t&31)==0) atomicAdd(&g_Z[pi], z);
    }
    __syncthreads();
    {
        int c=t&63, jg=t>>6;
        float ss=0.f, pm=0.f;
        #pragma unroll 8
        for(int j2=jg*16; j2<jg*16+16; j2++){
            float2 f = __half22float2(*(const __half2*)&Vs[c*130 + j2*2]);
            ss += f.x*es[2*j2] + f.y*es[2*j2+1];
            pm += f.x + f.y;
        }
        atomicAdd(&g_S[pi*64+c], ss);
        atomicAdd(&g_Pm[pi*64+c], pm);
    }
}

// ================ K4: per-pseudo-image finalize ================
__global__ void __launch_bounds__(64) k4(const float* __restrict__ chwv_w, const float* __restrict__ chwv_b,
                                         const float* __restrict__ chwz_w, const float* __restrict__ chwz_b,
                                         const float* __restrict__ ln_g,  const float* __restrict__ ln_b,
                                         const float* __restrict__ spwq_w,const float* __restrict__ spwq_b,
                                         const float* __restrict__ spwv_w,const float* __restrict__ spwv_b){
    int p = blockIdx.x, t = threadIdx.x;
    float hw = (p<16) ? 25600.f : ((p<160) ? 2916.f : 1024.f);
    __shared__ float xbar[64], pmean[64], wz[32], red[64], swq[32];

    float Zinv = 1.f/g_Z[p];
    xbar[t]  = g_S[p*64+t]*Zinv;
    pmean[t] = g_Pm[p*64+t]/hw;
    __syncthreads();

    if(t<32){
        float s = chwv_b[t];
        for(int c=0;c<64;c++) s += chwv_w[t*64+c]*xbar[c];
        wz[t]=s;
    }
    __syncthreads();

    float z = chwz_b[t];
    for(int j=0;j<32;j++) z += chwz_w[t*32+j]*wz[j];

    red[t]=z; __syncthreads();
    for(int s=32;s>0;s>>=1){ if(t<s) red[t]+=red[t+s]; __syncthreads(); }
    float mu = red[0]*(1.f/64.f); __syncthreads();
    float d = z-mu;
    red[t]=d*d; __syncthreads();
    for(int s=32;s>0;s>>=1){ if(t<s) red[t]+=red[t+s]; __syncthreads(); }
    float var = red[0]*(1.f/64.f);

    float zn = d*rsqrtf(var+1e-5f)*ln_g[t] + ln_b[t];
    g_gt[p*64+t] = sigf(zn);
    __syncthreads();

    if(t<32){
        float s = spwq_b[t];
        for(int c=0;c<64;c++) s += spwq_w[t*64+c]*pmean[c];
        float m=s;
        for(int off=16;off;off>>=1) m=fmaxf(m,__shfl_xor_sync(0xffffffffu,m,off));
        float e=expf(s-m), sum=e;
        for(int off=16;off;off>>=1) sum+=__shfl_xor_sync(0xffffffffu,sum,off);
        swq[t]=e/sum;
    }
    __syncthreads();

    float v=0.f;
    for(int j=0;j<32;j++) v += swq[j]*spwv_w[j*64+t];
    g_veff[p*64+t]=v;
    if(t==0){
        float b=0.f;
        for(int j=0;j<32;j++) b += swq[j]*spwv_b[j];
        g_beff[p]=b;
    }
}

// ================ K5: s-field (fp16 smem, q-tile 128) ================
__global__ void __launch_bounds__(256) k_sfield(const __half* __restrict__ ub, int khkw,
                                                size_t imgstride, int piBase,
                                                float* __restrict__ sf){
    __shared__ __half Vs[64*130];
    __shared__ float part[4*128];
    __shared__ float ve[64];
    int q0 = blockIdx.x*128, bp = blockIdx.y, n = blockIdx.z;
    int t = threadIdx.x;
    int pi = piBase + n*gridDim.y + bp;
    const __half* base = ub + (size_t)n*imgstride + (size_t)bp*64*khkw + q0;
    int qlim = khkw - q0; if(qlim>128) qlim=128;

    if(t<64) ve[t]=g_veff[pi*64+t];
    for(int i=t;i<4096;i+=256){
        int c=i>>6, j2=i&63;
        unsigned v = 0;
        if(j2*2 < qlim) v = *(const unsigned*)&base[(size_t)c*khkw + j2*2];
        *(unsigned*)&Vs[c*130 + j2*2] = v;
    }
    __syncthreads();
    {
        int j2=t&63, cg=t>>6;
        float sx=0.f, sy=0.f;
        #pragma unroll 8
        for(int cc=cg*16; cc<cg*16+16; cc++){
            float2 f = __half22float2(*(const __half2*)&Vs[cc*130 + j2*2]);
            float w = ve[cc];
            sx += w*f.x; sy += w*f.y;
        }
        part[cg*128 + j2*2]   = sx;
        part[cg*128 + j2*2+1] = sy;
    }
    __syncthreads();
    if(t<128 && t<qlim){
        float sd = part[t]+part[128+t]+part[256+t]+part[384+t] + g_beff[pi];
        sf[(size_t)n*(gridDim.y*khkw) + (size_t)bp*khkw + q0 + t] = sigf(sd);
    }
}

// ================ K6: s1 + div-free multiplier + HMMA GEMM ================
__global__ void __launch_bounds__(256) k6(const float* __restrict__ x, float* __restrict__ out){
    __shared__ __align__(16) float vs[192*PAD];      // ex tile fp32
    __shared__ __align__(16) __half vsh[32*264];     // GEMM input, px-major, pitch 264
    __shared__ float s1s[32], icntS[32];
    __shared__ int q5s[32], cp05s[32];
    __shared__ int q3s[4][32], cp03s[4][32];
    __shared__ int nsegS[32];

    int t = threadIdx.x;
    int wt = blockIdx.x, h = blockIdx.y, n = blockIdx.z;
    int w0 = wt*32;

    const __half* exg = g_ex + (size_t)n*NO*HW + (size_t)h*Wd + w0;
    for(int i=t;i<768;i+=256){
        int k=i>>2, q=(i&3)*8;
        uint4 raw = *(const uint4*)&exg[(size_t)k*HW + q];
        __half2* hp = (__half2*)&raw;
        float2 f0=__half22float2(hp[0]), f1=__half22float2(hp[1]);
        float2 f2=__half22float2(hp[2]), f3=__half22float2(hp[3]);
        float* d = &vs[k*PAD+q];
        d[0]=f0.x; d[1]=f0.y; d[2]=f1.x; d[3]=f1.y;
        d[4]=f2.x; d[5]=f2.y; d[6]=f3.x; d[7]=f3.y;
    }
    if(t<32){
        int w = w0 + t;
        int rp5 = ((h&31)*32 + (w&31))*P5 + (h>>5)*5 + (w>>5);
        q5s[t] = rp5 & 1023; cp05s[t] = rp5 >> 10;
        int R[2], C[2];
        int nr = cover3(h, R), nc = cover3(w, C);
        nsegS[t] = nr*nc;
        icntS[t] = 1.f/(float)(nr*nc);
        for(int ri=0;ri<nr;ri++)
            for(int cj=0;cj<nc;cj++){
                int ph=R[ri], pw=C[cj];
                int rp3 = ((h-53*ph)*54 + (w-53*pw))*P3 + ph*3 + pw;
                int s = ri*nc + cj;
                cp03s[s][t] = rp3 / KHKW3;
                q3s[s][t]   = rp3 % KHKW3;
            }
    }
    __syncthreads();

    // x -> vsh rows 192..255 (fp16, transposed layout)
    const float* xp = x + (size_t)n*64*HW + (size_t)h*Wd + w0;
    for(int i=t;i<2048;i+=256){
        int c=i>>5, px=i&31;
        vsh[px*264 + 192 + c] = __float2half(xp[(size_t)c*HW+px]);
    }
    // win1 s-field from raw chunk0
    if(t<32){
        float sd = g_beff[n];
        const float* ve = &g_veff[n*64];
        #pragma unroll
        for(int c=0;c<64;c++) sd += ve[c]*vs[c*PAD+t];
        s1s[t] = sigf(sd);
    }
    __syncthreads();

    // multiplier (div-free) -> vsh rows 0..191
    for(int i=t;i<NO*32;i+=256){
        int k=i>>5, pix=i&31, win=k>>6, ci=k&63;
        float m;
        if(win==0){
            m = g_gt[n*64+ci] + s1s[pix];
        } else if(win==2){
            int cpv = cp05s[pix] + 25*ci;
            int bp = cpv>>6, cp = cpv&63;
            m = g_gt[(160+n*25+bp)*64+cp] + g_sf5[n*25600 + (bp<<10) + q5s[pix]];
        } else {
            m = 0.f;
            int ns = nsegS[pix];
            #pragma unroll
            for(int s=0;s<4;s++){
                if(s>=ns) break;
                int cpv = cp03s[s][pix] + 9*ci;
                int bp = cpv>>6, cp = cpv&63;
                m += g_gt[(16+n*9+bp)*64+cp] + g_sf3[n*A3 + bp*KHKW3 + q3s[s][pix]];
            }
            m *= icntS[pix];
        }
        vsh[pix*264 + k] = __float2half(vs[k*PAD+pix]*(1.f + m));
    }
    __syncthreads();

    // HMMA GEMM: out[64ob][32px] = Wall^T[64][256] @ vsh[256][32]
    int lane = t&31, w = t>>5;
    int g = lane>>2, tig = lane&3;
    int mt = w&3, nt0 = (w>>2)*2, nt1 = nt0+1;
    int ob0 = mt*16;

    float vb0 = __ldg(&g_vb[ob0+g]), vb1 = __ldg(&g_vb[ob0+g+8]);
    float c00=vb0, c01=vb0, c02=vb1, c03=vb1;
    float c10=vb0, c11=vb0, c12=vb1, c13=vb1;

    const uint4* wa = g_WhA4 + mt*512 + lane;
    const __half* b0base = &vsh[(nt0*8+g)*264 + tig*2];
    const __half* b1base = &vsh[(nt1*8+g)*264 + tig*2];

    #pragma unroll
    for(int kt=0;kt<16;kt++){
        uint4 a = __ldg(&wa[kt*32]);
        int k0 = kt*16;
        unsigned p00 = *(const unsigned*)&b0base[k0];
        unsigned p01 = *(const unsigned*)&b0base[k0+8];
        MMA16816(c00,c01,c02,c03, a, p00,p01);
        unsigned p10 = *(const unsigned*)&b1base[k0];
        unsigned p11 = *(const unsigned*)&b1base[k0+8];
        MMA16816(c10,c11,c12,c13, a, p10,p11);
    }

    float* og = out + (size_t)n*64*HW + (size_t)h*Wd + w0;
    int px0 = nt0*8 + tig*2, px1 = nt1*8 + tig*2;
    *(float2*)&og[(size_t)(ob0+g  )*HW + px0] = make_float2(c00,c01);
    *(float2*)&og[(size_t)(ob0+g+8)*HW + px0] = make_float2(c02,c03);
    *(float2*)&og[(size_t)(ob0+g  )*HW + px1] = make_float2(c10,c11);
    *(float2*)&og[(size_t)(ob0+g+8)*HW + px1] = make_float2(c12,c13);
}

// ================ launch ================
extern "C" void kernel_launch(void* const* d_in, const int* in_sizes, int n_in,
                              void* d_out, int out_size){
    const float* x      = (const float*)d_in[0];
    const float* exp_w  = (const float*)d_in[1];
    const float* exp_b  = (const float*)d_in[2];
    const float* res_w  = (const float*)d_in[3];
    const float* res_b  = (const float*)d_in[4];
    const float* fus_w  = (const float*)d_in[5];
    const float* fus_b  = (const float*)d_in[6];
    const float* chwv_w = (const float*)d_in[7];
    const float* chwv_b = (const float*)d_in[8];
    const float* chwq_w = (const float*)d_in[9];
    const float* chwq_b = (const float*)d_in[10];
    const float* chwz_w = (const float*)d_in[11];
    const float* chwz_b = (const float*)d_in[12];
    const float* ln_g   = (const float*)d_in[13];
    const float* ln_b   = (const float*)d_in[14];
    const float* spwv_w = (const float*)d_in[15];
    const float* spwv_b = (const float*)d_in[16];
    const float* spwq_w = (const float*)d_in[17];
    const float* spwq_b = (const float*)d_in[18];
    float* out = (float*)d_out;

    __half *g_u3_p, *g_u5_p;
    float *g_sf3_p, *g_sf5_p;
    cudaGetSymbolAddress((void**)&g_u3_p, g_u3);
    cudaGetSymbolAddress((void**)&g_u5_p, g_u5);
    cudaGetSymbolAddress((void**)&g_sf3_p, g_sf3);
    cudaGetSymbolAddress((void**)&g_sf5_p, g_sf5);

    k_zero<<<(NPI*64+255)/256, 256>>>();
    k_wprep<<<1, 256>>>(exp_w, res_w, res_b, fus_w, fus_b);

    dim3 grid(Wd/32, Hh, NIMG);
    k1<<<grid, 256>>>(x, exp_b, chwq_w, chwq_b);

    k2_5<<<dim3(32,NIMG), 256>>>();
    k2_3<<<dim3(54,NIMG), 256>>>();

    k_stats<<<dim3(23,  9, NIMG), 256>>>(g_u3_p, KHKW3,(size_t)U3IMG, 16,  chwq_w, chwq_b);
    k_stats<<<dim3(8,  25, NIMG), 256>>>(g_u5_p, KHKW5,(size_t)U5IMG, 160, chwq_w, chwq_b);

    k4<<<NPI, 64>>>(chwv_w, chwv_b, chwz_w, chwz_b, ln_g, ln_b,
                    spwq_w, spwq_b, spwv_w, spwv_b);

    k_sfield<<<dim3(23,  9, NIMG), 256>>>(g_u3_p, KHKW3,(size_t)U3IMG, 16,  g_sf3_p);
    k_sfield<<<dim3(8,  25, NIMG), 256>>>(g_u5_p, KHKW5,(size_t)U5IMG, 160, g_sf5_p);

    k6<<<grid, 256>>>(x, out);
}

// round 11
// speedup vs baseline: 2.3232x; 1.1441x over previous
#include <cuda_runtime.h>
#include <cuda_fp16.h>
#include <math.h>

typedef unsigned long long u64;

#define NIMG 16
#define NO   192
#define Hh   160
#define Wd   160
#define HW   25600
#define PAD  36

#define KHKW3 2916
#define P3    9
#define A3    26244
#define U3IMG 1679616
#define KHKW5 1024
#define P5    25
#define A5    25600
#define U5IMG 1638400
#define NPI   560

// ---------------- scratch ----------------
__device__ __align__(16) __half g_ex[(size_t)NIMG*NO*HW];
__device__ __align__(16) __half g_u3[(size_t)NIMG*U3IMG];
__device__ __align__(16) __half g_u5[(size_t)NIMG*U5IMG];
__device__ __align__(16) float g_sf3[NIMG*P3*KHKW3];
__device__ __align__(16) float g_sf5[NIMG*P5*KHKW5];
__device__ float g_Z[NPI], g_S[NPI*64], g_Pm[NPI*64];
__device__ float g_gt[NPI*64], g_veff[NPI*64], g_beff[NPI];
__device__ __align__(16) float g_Wall[256*64];   // rows 0..191: fus@res [k][o]; 192..255: fus^T [c][o]
__device__ __align__(16) uint4 g_WhA4[4*16*32];  // K6 HMMA A-fragments [mt][kt][lane]
__device__ __align__(16) uint4 g_WK1A4[12*4*32]; // K1 HMMA A-fragments [mt][kt][lane]
__device__ float g_vb[64];
__device__ __align__(16) float g_expWt[64*NO];   // [c][o]

// ---------------- helpers ----------------
__device__ __forceinline__ float sigf(float x){ return 1.f/(1.f+expf(-x)); }
__device__ __forceinline__ int cover3(int h, int* r){
    int n=0;
    #pragma unroll
    for(int i=0;i<3;i++){ int lo=53*i; if(h>=lo && h<=lo+53) r[n++]=i; }
    return n;
}
__device__ __forceinline__ unsigned h2pack(float a, float b){
    __half2 h = __floats2half2_rn(a,b);
    return *(unsigned*)&h;
}

#define MMA16816(c0,c1,c2,c3,a,b0,b1) \
    asm volatile("mma.sync.aligned.m16n8k16.row.col.f32.f16.f16.f32 " \
        "{%0,%1,%2,%3},{%4,%5,%6,%7},{%8,%9},{%0,%1,%2,%3};" \
        : "+f"(c0),"+f"(c1),"+f"(c2),"+f"(c3) \
        : "r"((a).x),"r"((a).y),"r"((a).z),"r"((a).w),"r"(b0),"r"(b1))

// ================ K0a: zero accumulators ================
__global__ void k_zero(){
    int i = blockIdx.x*256 + threadIdx.x;
    if(i < NPI) g_Z[i]=0.f;
    if(i < NPI*64){ g_S[i]=0.f; g_Pm[i]=0.f; }
}

// ================ K0b: weight prep ================
__global__ void k_wprep(const float* __restrict__ exp_w, const float* __restrict__ res_w,
                        const float* __restrict__ res_b, const float* __restrict__ fus_w,
                        const float* __restrict__ fus_b){
    int t = threadIdx.x;
    for(int i=t;i<64*NO;i+=256){ int c=i/NO, o=i%NO; g_expWt[i]=exp_w[o*64+c]; }
    for(int i=t;i<NO*64;i+=256){
        int k=i/64, o=i%64; float s=0.f;
        for(int c=0;c<64;c++) s += fus_w[o*64+c]*res_w[c*NO+k];
        g_Wall[i]=s;
    }
    for(int i=t;i<64*64;i+=256){ int c=i/64, o=i%64; g_Wall[(192+c)*64+o]=fus_w[o*64+c]; }
    for(int o=t;o<64;o+=256){
        float s=fus_b[o];
        for(int c=0;c<64;c++) s += fus_w[o*64+c]*res_b[c];
        g_vb[o]=s;
    }
    __syncthreads();
    // K6 A-fragments from g_Wall [k][m], stride 64
    for(int i=t;i<2048;i+=256){
        int mt = i>>9, kt = (i>>5)&15, lane = i&31;
        int g = lane>>2, tig = lane&3;
        int k0 = kt*16, ob0 = mt*16;
        const float* W = g_Wall;
        unsigned r0 = h2pack(W[(k0+tig*2)*64+ob0+g],     W[(k0+tig*2+1)*64+ob0+g]);
        unsigned r1 = h2pack(W[(k0+tig*2)*64+ob0+g+8],   W[(k0+tig*2+1)*64+ob0+g+8]);
        unsigned r2 = h2pack(W[(k0+tig*2+8)*64+ob0+g],   W[(k0+tig*2+9)*64+ob0+g]);
        unsigned r3 = h2pack(W[(k0+tig*2+8)*64+ob0+g+8], W[(k0+tig*2+9)*64+ob0+g+8]);
        g_WhA4[i] = make_uint4(r0,r1,r2,r3);
    }
    // K1 A-fragments from g_expWt [k][m], stride NO
    for(int i=t;i<1536;i+=256){
        int mt = i>>7, kt = (i>>5)&3, lane = i&31;
        int g = lane>>2, tig = lane&3;
        int k0 = kt*16, ob0 = mt*16;
        const float* W = g_expWt;
        unsigned r0 = h2pack(W[(k0+tig*2)*NO+ob0+g],     W[(k0+tig*2+1)*NO+ob0+g]);
        unsigned r1 = h2pack(W[(k0+tig*2)*NO+ob0+g+8],   W[(k0+tig*2+1)*NO+ob0+g+8]);
        unsigned r2 = h2pack(W[(k0+tig*2+8)*NO+ob0+g],   W[(k0+tig*2+9)*NO+ob0+g]);
        unsigned r3 = h2pack(W[(k0+tig*2+8)*NO+ob0+g+8], W[(k0+tig*2+9)*NO+ob0+g+8]);
        g_WK1A4[i] = make_uint4(r0,r1,r2,r3);
    }
}

// ================ K1: HMMA ex = Wexp @ x + fused win1 stats ================
__global__ void __launch_bounds__(256) k1(const float* __restrict__ x,
                                          const float* __restrict__ exp_b,
                                          const float* __restrict__ wq,
                                          const float* __restrict__ wqb){
    __shared__ __align__(16) __half xh[32*72];     // [px][c], pitch 72 halves
    __shared__ __align__(16) __half exsh[192*40];  // [ob][px], pitch 40 halves
    __shared__ float es[32];
    int t = threadIdx.x;
    int wt = blockIdx.x, h = blockIdx.y, n = blockIdx.z;
    int w0 = wt*32;

    const float* xp = x + (size_t)n*64*HW + (size_t)h*Wd + w0;
    for(int i=t;i<512;i+=256){
        int c=i>>3, p4=(i&7)*4;
        float4 v = *(const float4*)&xp[(size_t)c*HW + p4];
        xh[(p4  )*72 + c] = __float2half(v.x);
        xh[(p4+1)*72 + c] = __float2half(v.y);
        xh[(p4+2)*72 + c] = __float2half(v.z);
        xh[(p4+3)*72 + c] = __float2half(v.w);
    }
    __syncthreads();

    int lane = t&31, w = t>>5;
    int g = lane>>2, tig = lane&3;
    int mtb = (w&3)*3, nt0 = (w>>2)*2, nt1 = nt0+1;
    int px0 = nt0*8 + tig*2, px1 = nt1*8 + tig*2;

    const __half* b0base = &xh[(nt0*8+g)*72 + tig*2];
    const __half* b1base = &xh[(nt1*8+g)*72 + tig*2];
    unsigned bf0[8], bf1[8];
    #pragma unroll
    for(int kt=0;kt<4;kt++){
        bf0[kt*2  ] = *(const unsigned*)&b0base[kt*16];
        bf0[kt*2+1] = *(const unsigned*)&b0base[kt*16+8];
        bf1[kt*2  ] = *(const unsigned*)&b1base[kt*16];
        bf1[kt*2+1] = *(const unsigned*)&b1base[kt*16+8];
    }

    #pragma unroll
    for(int mi=0;mi<3;mi++){
        int mt = mtb+mi, ob0 = mt*16;
        float c00=0,c01=0,c02=0,c03=0, c10=0,c11=0,c12=0,c13=0;
        const uint4* wa = g_WK1A4 + mt*128 + lane;
        #pragma unroll
        for(int kt=0;kt<4;kt++){
            uint4 a = __ldg(&wa[kt*32]);
            MMA16816(c00,c01,c02,c03, a, bf0[kt*2],bf0[kt*2+1]);
            MMA16816(c10,c11,c12,c13, a, bf1[kt*2],bf1[kt*2+1]);
        }
        float b0 = __ldg(&exp_b[ob0+g]), b1 = __ldg(&exp_b[ob0+g+8]);
        *(unsigned*)&exsh[(ob0+g  )*40 + px0] = h2pack(c00+b0, c01+b0);
        *(unsigned*)&exsh[(ob0+g+8)*40 + px0] = h2pack(c02+b1, c03+b1);
        *(unsigned*)&exsh[(ob0+g  )*40 + px1] = h2pack(c10+b0, c11+b0);
        *(unsigned*)&exsh[(ob0+g+8)*40 + px1] = h2pack(c12+b1, c13+b1);
    }
    __syncthreads();

    __half* exg = g_ex + (size_t)n*NO*HW + (size_t)h*Wd + w0;
    for(int i=t;i<768;i+=256){
        int r=i>>2, q=(i&3)*8;
        *(uint4*)&exg[(size_t)r*HW + q] = *(const uint4*)&exsh[r*40 + q];
    }

    if(t<32){
        float qd = wqb[0];
        #pragma unroll
        for(int c=0;c<64;c++) qd += wq[c]*__half2float(exsh[c*40+t]);
        float e = expf(qd);
        es[t]=e;
        float z=e;
        for(int off=16;off;off>>=1) z += __shfl_xor_sync(0xffffffffu,z,off);
        if(t==0) atomicAdd(&g_Z[n], z);
    }
    __syncthreads();
    if(t<64){
        float Ps=0.f, Ss=0.f;
        #pragma unroll
        for(int px=0;px<32;px++){ float v=__half2float(exsh[t*40+px]); Ps+=v; Ss+=v*es[px]; }
        atomicAdd(&g_S[n*64+t], Ss);
        atomicAdd(&g_Pm[n*64+t], Ps);
    }
}

// ================ K2: repack into unfold order (warp-per-ci, fp16) ================
__global__ void __launch_bounds__(256) k2_5(){
    __shared__ __align__(16) __half rb[8][800];
    int y = blockIdx.x, n = blockIdx.y;
    int wp = threadIdx.x >> 5, lane = threadIdx.x & 31;
    for(int cit=0; cit<8; cit++){
        int ci = cit*8 + wp;
        const __half* src = g_ex + (size_t)n*NO*HW + (size_t)(128+ci)*HW;
        #pragma unroll
        for(int ph=0; ph<5; ph++){
            const __half2* row2 = (const __half2*)(src + (size_t)(ph*32+y)*Wd);
            #pragma unroll
            for(int it=0; it<3; it++){
                int idx = lane + it*32;
                if(idx<80){
                    __half2 v = row2[idx];
                    int w = idx*2, pw = w>>5, xx = w&31;
                    rb[wp][xx*25 + ph*5 + pw]     = __low2half(v);
                    rb[wp][(xx+1)*25 + ph*5 + pw] = __high2half(v);
                }
            }
        }
        __syncwarp();
        uint4* dst = (uint4*)(g_u5 + (size_t)n*U5IMG + (size_t)(ci*1024 + y*32)*25);
        const uint4* s = (const uint4*)rb[wp];
        #pragma unroll
        for(int it=0; it<4; it++){
            int k = lane + it*32;
            if(k < 100) dst[k] = s[k];
        }
        __syncwarp();
    }
}
__global__ void __launch_bounds__(256) k2_3(){
    __shared__ __align__(16) __half rb[8][488];
    int yy = blockIdx.x, n = blockIdx.y;
    int wp = threadIdx.x >> 5, lane = threadIdx.x & 31;
    for(int cit=0; cit<8; cit++){
        int ci = cit*8 + wp;
        const __half* src = g_ex + (size_t)n*NO*HW + (size_t)(64+ci)*HW;
        #pragma unroll
        for(int ph=0; ph<3; ph++){
            const __half2* row2 = (const __half2*)(src + (size_t)(53*ph+yy)*Wd);
            #pragma unroll
            for(int it=0; it<3; it++){
                int idx = lane + it*32;
                if(idx<80){
                    __half2 v = row2[idx];
                    int w0_ = idx*2;
                    __half hv[2] = {__low2half(v), __high2half(v)};
                    #pragma unroll
                    for(int hh=0; hh<2; hh++){
                        int w = w0_ + hh;
                        #pragma unroll
                        for(int pw=0; pw<3; pw++){
                            int xx = w - 53*pw;
                            if(xx>=0 && xx<54) rb[wp][xx*9 + ph*3 + pw] = hv[hh];
                        }
                    }
                }
            }
        }
        __syncwarp();
        unsigned* dst = (unsigned*)(g_u3 + (size_t)n*U3IMG + (size_t)ci*A3 + (size_t)yy*486);
        const unsigned* s = (const unsigned*)rb[wp];
        #pragma unroll
        for(int it=0; it<8; it++){
            int k = lane + it*32;
            if(k < 243) dst[k] = s[k];
        }
        __syncwarp();
    }
}

// ================ K3: stats (fp16 smem, q-tile 128) ================
__global__ void __launch_bounds__(256) k_stats(const __half* __restrict__ ub, int khkw,
                                               size_t imgstride, int piBase,
                                               const float* __restrict__ wq,
                                               const float* __restrict__ wqb){
    __shared__ __half Vs[64*130];
    __shared__ float part[4*128];
    __shared__ float es[128];
    int q0 = blockIdx.x*128, bp = blockIdx.y, n = blockIdx.z;
    int t = threadIdx.x;
    const __half* base = ub + (size_t)n*imgstride + (size_t)bp*64*khkw + q0;
    int qlim = khkw - q0; if(qlim>128) qlim=128;

    for(int i=t;i<4096;i+=256){
        int c=i>>6, j2=i&63;
        unsigned v = 0;
        if(j2*2 < qlim) v = *(const unsigned*)&base[(size_t)c*khkw + j2*2];
        *(unsigned*)&Vs[c*130 + j2*2] = v;
    }
    __syncthreads();
    {
        int j2=t&63, cg=t>>6;
        float sx=0.f, sy=0.f;
        #pragma unroll 8
        for(int cc=cg*16; cc<cg*16+16; cc++){
            float2 f = __half22float2(*(const __half2*)&Vs[cc*130 + j2*2]);
            float w = wq[cc];
            sx += w*f.x; sy += w*f.y;
        }
        part[cg*128 + j2*2]   = sx;
        part[cg*128 + j2*2+1] = sy;
    }
    __syncthreads();
    int pi = piBase + n*gridDim.y + bp;
    if(t<128){
        float qd = part[t]+part[128+t]+part[256+t]+part[384+t] + wqb[0];
        float e = (t<qlim) ? expf(qd) : 0.f;
        es[t]=e;
        float z=e;
        for(int off=16;off;off>>=1) z += __shfl_xor_sync(0xffffffffu,z,off);
        if((t&31)==0) atomicAdd(&g_Z[pi], z);
    }
    __syncthreads();
    {
        int c=t&63, jg=t>>6;
        float ss=0.f, pm=0.f;
        #pragma unroll 8
        for(int j2=jg*16; j2<jg*16+16; j2++){
            float2 f = __half22float2(*(const __half2*)&Vs[c*130 + j2*2]);
            ss += f.x*es[2*j2] + f.y*es[2*j2+1];
            pm += f.x + f.y;
        }
        atomicAdd(&g_S[pi*64+c], ss);
        atomicAdd(&g_Pm[pi*64+c], pm);
    }
}

// ================ K4: per-pseudo-image finalize ================
__global__ void __launch_bounds__(64) k4(const float* __restrict__ chwv_w, const float* __restrict__ chwv_b,
                                         const float* __restrict__ chwz_w, const float* __restrict__ chwz_b,
                                         const float* __restrict__ ln_g,  const float* __restrict__ ln_b,
                                         const float* __restrict__ spwq_w,const float* __restrict__ spwq_b,
                                         const float* __restrict__ spwv_w,const float* __restrict__ spwv_b){
    int p = blockIdx.x, t = threadIdx.x;
    float hw = (p<16) ? 25600.f : ((p<160) ? 2916.f : 1024.f);
    __shared__ float xbar[64], pmean[64], wz[32], red[64], swq[32];

    float Zinv = 1.f/g_Z[p];
    xbar[t]  = g_S[p*64+t]*Zinv;
    pmean[t] = g_Pm[p*64+t]/hw;
    __syncthreads();

    if(t<32){
        float s = chwv_b[t];
        for(int c=0;c<64;c++) s += chwv_w[t*64+c]*xbar[c];
        wz[t]=s;
    }
    __syncthreads();

    float z = chwz_b[t];
    for(int j=0;j<32;j++) z += chwz_w[t*32+j]*wz[j];

    red[t]=z; __syncthreads();
    for(int s=32;s>0;s>>=1){ if(t<s) red[t]+=red[t+s]; __syncthreads(); }
    float mu = red[0]*(1.f/64.f); __syncthreads();
    float d = z-mu;
    red[t]=d*d; __syncthreads();
    for(int s=32;s>0;s>>=1){ if(t<s) red[t]+=red[t+s]; __syncthreads(); }
    float var = red[0]*(1.f/64.f);

    float zn = d*rsqrtf(var+1e-5f)*ln_g[t] + ln_b[t];
    g_gt[p*64+t] = sigf(zn);
    __syncthreads();

    if(t<32){
        float s = spwq_b[t];
        for(int c=0;c<64;c++) s += spwq_w[t*64+c]*pmean[c];
        float m=s;
        for(int off=16;off;off>>=1) m=fmaxf(m,__shfl_xor_sync(0xffffffffu,m,off));
        float e=expf(s-m), sum=e;
        for(int off=16;off;off>>=1) sum+=__shfl_xor_sync(0xffffffffu,sum,off);
        swq[t]=e/sum;
    }
    __syncthreads();

    float v=0.f;
    for(int j=0;j<32;j++) v += swq[j]*spwv_w[j*64+t];
    g_veff[p*64+t]=v;
    if(t==0){
        float b=0.f;
        for(int j=0;j<32;j++) b += swq[j]*spwv_b[j];
        g_beff[p]=b;
    }
}

// ================ K5: s-field (fp16 smem, q-tile 128) ================
__global__ void __launch_bounds__(256) k_sfield(const __half* __restrict__ ub, int khkw,
                                                size_t imgstride, int piBase,
                                                float* __restrict__ sf){
    __shared__ __half Vs[64*130];
    __shared__ float part[4*128];
    __shared__ float ve[64];
    int q0 = blockIdx.x*128, bp = blockIdx.y, n = blockIdx.z;
    int t = threadIdx.x;
    int pi = piBase + n*gridDim.y + bp;
    const __half* base = ub + (size_t)n*imgstride + (size_t)bp*64*khkw + q0;
    int qlim = khkw - q0; if(qlim>128) qlim=128;

    if(t<64) ve[t]=g_veff[pi*64+t];
    for(int i=t;i<4096;i+=256){
        int c=i>>6, j2=i&63;
        unsigned v = 0;
        if(j2*2 < qlim) v = *(const unsigned*)&base[(size_t)c*khkw + j2*2];
        *(unsigned*)&Vs[c*130 + j2*2] = v;
    }
    __syncthreads();
    {
        int j2=t&63, cg=t>>6;
        float sx=0.f, sy=0.f;
        #pragma unroll 8
        for(int cc=cg*16; cc<cg*16+16; cc++){
            float2 f = __half22float2(*(const __half2*)&Vs[cc*130 + j2*2]);
            float w = ve[cc];
            sx += w*f.x; sy += w*f.y;
        }
        part[cg*128 + j2*2]   = sx;
        part[cg*128 + j2*2+1] = sy;
    }
    __syncthreads();
    if(t<128 && t<qlim){
        float sd = part[t]+part[128+t]+part[256+t]+part[384+t] + g_beff[pi];
        sf[(size_t)n*(gridDim.y*khkw) + (size_t)bp*khkw + q0 + t] = sigf(sd);
    }
}

// ================ K6: vsh-only multiplier + HMMA GEMM ================
__global__ void __launch_bounds__(256) k6(const float* __restrict__ x, float* __restrict__ out){
    __shared__ __align__(16) __half vsh[32*264];     // [px][k], rows 192..255 = x
    __shared__ float s1s[32], icntS[32];
    __shared__ int q5s[32], cp05s[32];
    __shared__ int q3s[4][32], cp03s[4][32];
    __shared__ int nsegS[32];

    int t = threadIdx.x;
    int wt = blockIdx.x, h = blockIdx.y, n = blockIdx.z;
    int w0 = wt*32;

    // ex tile -> vsh (fp16 passthrough, scatter to px-major)
    const __half* exg = g_ex + (size_t)n*NO*HW + (size_t)h*Wd + w0;
    for(int i=t;i<768;i+=256){
        int k=i>>2, q=(i&3)*8;
        uint4 raw = *(const uint4*)&exg[(size_t)k*HW + q];
        const __half* hp = (const __half*)&raw;
        #pragma unroll
        for(int j=0;j<8;j++) vsh[(q+j)*264 + k] = hp[j];
    }
    // x -> vsh rows 192..255
    const float* xp = x + (size_t)n*64*HW + (size_t)h*Wd + w0;
    for(int i=t;i<2048;i+=256){
        int c=i>>5, px=i&31;
        vsh[px*264 + 192 + c] = __float2half(xp[(size_t)c*HW+px]);
    }
    if(t<32){
        int w = w0 + t;
        int rp5 = ((h&31)*32 + (w&31))*P5 + (h>>5)*5 + (w>>5);
        q5s[t] = rp5 & 1023; cp05s[t] = rp5 >> 10;
        int R[2], C[2];
        int nr = cover3(h, R), nc = cover3(w, C);
        nsegS[t] = nr*nc;
        icntS[t] = 1.f/(float)(nr*nc);
        for(int ri=0;ri<nr;ri++)
            for(int cj=0;cj<nc;cj++){
                int ph=R[ri], pw=C[cj];
                int rp3 = ((h-53*ph)*54 + (w-53*pw))*P3 + ph*3 + pw;
                int s = ri*nc + cj;
                cp03s[s][t] = rp3 / KHKW3;
                q3s[s][t]   = rp3 % KHKW3;
            }
    }
    __syncthreads();

    // win1 s-field from vsh chunk0 (unscaled)
    if(t<32){
        float sd = g_beff[n];
        const float* ve = &g_veff[n*64];
        #pragma unroll
        for(int c=0;c<64;c++) sd += ve[c]*__half2float(vsh[t*264+c]);
        s1s[t] = sigf(sd);
    }
    __syncthreads();

    // multiplier: 96 k-pairs x 32 px; lane -> k-within-chunk (conflict-free half2 RMW)
    {
        int lane = t&31, wp = t>>5;
        int ci0 = lane*2;
        #pragma unroll
        for(int j=0;j<12;j++){
            int idx = wp + j*8;           // 0..95
            int g32 = idx>>5, pix = idx&31;
            int k = (g32<<6) + ci0;
            __half2* cell = (__half2*)&vsh[pix*264 + k];
            float2 exv = __half22float2(*cell);
            float m0, m1;
            if(g32==0){
                float s1 = s1s[pix];
                m0 = g_gt[n*64+ci0  ] + s1;
                m1 = g_gt[n*64+ci0+1] + s1;
            } else if(g32==2){
                int q5 = q5s[pix];
                int cpv0 = cp05s[pix] + 25*ci0;
                int cpv1 = cpv0 + 25;
                int bp0=cpv0>>6, cp0=cpv0&63, bp1=cpv1>>6, cp1=cpv1&63;
                m0 = g_gt[(160+n*25+bp0)*64+cp0] + g_sf5[n*25600 + (bp0<<10) + q5];
                m1 = g_gt[(160+n*25+bp1)*64+cp1] + g_sf5[n*25600 + (bp1<<10) + q5];
            } else {
                m0 = 0.f; m1 = 0.f;
                int ns = nsegS[pix];
                #pragma unroll
                for(int s=0;s<4;s++){
                    if(s>=ns) break;
                    int q3 = q3s[s][pix];
                    int cpv0 = cp03s[s][pix] + 9*ci0;
                    int cpv1 = cpv0 + 9;
                    int bp0=cpv0>>6, cp0=cpv0&63, bp1=cpv1>>6, cp1=cpv1&63;
                    m0 += g_gt[(16+n*9+bp0)*64+cp0] + g_sf3[n*A3 + bp0*KHKW3 + q3];
                    m1 += g_gt[(16+n*9+bp1)*64+cp1] + g_sf3[n*A3 + bp1*KHKW3 + q3];
                }
                float ic = icntS[pix];
                m0 *= ic; m1 *= ic;
            }
            exv.x *= (1.f + m0);
            exv.y *= (1.f + m1);
            *cell = __floats2half2_rn(exv.x, exv.y);
        }
    }
    __syncthreads();

    // HMMA GEMM: out[64ob][32px] = Wall^T[64][256] @ vsh[256][32]
    int lane = t&31, w = t>>5;
    int g = lane>>2, tig = lane&3;
    int mt = w&3, nt0 = (w>>2)*2, nt1 = nt0+1;
    int ob0 = mt*16;

    float vb0 = __ldg(&g_vb[ob0+g]), vb1 = __ldg(&g_vb[ob0+g+8]);
    float c00=vb0, c01=vb0, c02=vb1, c03=vb1;
    float c10=vb0, c11=vb0, c12=vb1, c13=vb1;

    const uint4* wa = g_WhA4 + mt*512 + lane;
    const __half* b0base = &vsh[(nt0*8+g)*264 + tig*2];
    const __half* b1base = &vsh[(nt1*8+g)*264 + tig*2];

    #pragma unroll
    for(int kt=0;kt<16;kt++){
        uint4 a = __ldg(&wa[kt*32]);
        int k0 = kt*16;
        unsigned p00 = *(const unsigned*)&b0base[k0];
        unsigned p01 = *(const unsigned*)&b0base[k0+8];
        MMA16816(c00,c01,c02,c03, a, p00,p01);
        unsigned p10 = *(const unsigned*)&b1base[k0];
        unsigned p11 = *(const unsigned*)&b1base[k0+8];
        MMA16816(c10,c11,c12,c13, a, p10,p11);
    }

    float* og = out + (size_t)n*64*HW + (size_t)h*Wd + w0;
    int px0 = nt0*8 + tig*2, px1 = nt1*8 + tig*2;
    *(float2*)&og[(size_t)(ob0+g  )*HW + px0] = make_float2(c00,c01);
    *(float2*)&og[(size_t)(ob0+g+8)*HW + px0] = make_float2(c02,c03);
    *(float2*)&og[(size_t)(ob0+g  )*HW + px1] = make_float2(c10,c11);
    *(float2*)&og[(size_t)(ob0+g+8)*HW + px1] = make_float2(c12,c13);
}

// ================ launch ================
extern "C" void kernel_launch(void* const* d_in, const int* in_sizes, int n_in,
                              void* d_out, int out_size){
    const float* x      = (const float*)d_in[0];
    const float* exp_w  = (const float*)d_in[1];
    const float* exp_b  = (const float*)d_in[2];
    const float* res_w  = (const float*)d_in[3];
    const float* res_b  = (const float*)d_in[4];
    const float* fus_w  = (const float*)d_in[5];
    const float* fus_b  = (const float*)d_in[6];
    const float* chwv_w = (const float*)d_in[7];
    const float* chwv_b = (const float*)d_in[8];
    const float* chwq_w = (const float*)d_in[9];
    const float* chwq_b = (const float*)d_in[10];
    const float* chwz_w = (const float*)d_in[11];
    const float* chwz_b = (const float*)d_in[12];
    const float* ln_g   = (const float*)d_in[13];
    const float* ln_b   = (const float*)d_in[14];
    const float* spwv_w = (const float*)d_in[15];
    const float* spwv_b = (const float*)d_in[16];
    const float* spwq_w = (const float*)d_in[17];
    const float* spwq_b = (const float*)d_in[18];
    float* out = (float*)d_out;

    __half *g_u3_p, *g_u5_p;
    float *g_sf3_p, *g_sf5_p;
    cudaGetSymbolAddress((void**)&g_u3_p, g_u3);
    cudaGetSymbolAddress((void**)&g_u5_p, g_u5);
    cudaGetSymbolAddress((void**)&g_sf3_p, g_sf3);
    cudaGetSymbolAddress((void**)&g_sf5_p, g_sf5);

    k_zero<<<(NPI*64+255)/256, 256>>>();
    k_wprep<<<1, 256>>>(exp_w, res_w, res_b, fus_w, fus_b);

    dim3 grid(Wd/32, Hh, NIMG);
    k1<<<grid, 256>>>(x, exp_b, chwq_w, chwq_b);

    k2_5<<<dim3(32,NIMG), 256>>>();
    k2_3<<<dim3(54,NIMG), 256>>>();

    k_stats<<<dim3(23,  9, NIMG), 256>>>(g_u3_p, KHKW3,(size_t)U3IMG, 16,  chwq_w, chwq_b);
    k_stats<<<dim3(8,  25, NIMG), 256>>>(g_u5_p, KHKW5,(size_t)U5IMG, 160, chwq_w, chwq_b);

    k4<<<NPI, 64>>>(chwv_w, chwv_b, chwz_w, chwz_b, ln_g, ln_b,
                    spwq_w, spwq_b, spwv_w, spwv_b);

    k_sfield<<<dim3(23,  9, NIMG), 256>>>(g_u3_p, KHKW3,(size_t)U3IMG, 16,  g_sf3_p);
    k_sfield<<<dim3(8,  25, NIMG), 256>>>(g_u5_p, KHKW5,(size_t)U5IMG, 160, g_sf5_p);

    k6<<<grid, 256>>>(x, out);
}